// round 1
// baseline (speedup 1.0000x reference)
#include <cuda_runtime.h>
#include <math.h>

#define BSZ 4
#define CCH 256
#define HW  4096

#define BM 128
#define BN 128
#define BK 8
#define ASTR (BK + 1)
#define NTHR 256
#define SMEMF (BM * ASTR + BK * BN) /* 1152 + 1024 = 2176 floats */

// ---------------- scratch (no cudaMalloc allowed) ----------------
static __device__ float g_ec[(size_t)BSZ * CCH * HW];     // [b][d][n] 16MB
static __device__ float g_E[(size_t)BSZ * HW * HW];       // [b][n][m] 268MB
static __device__ float g_qatt[(size_t)BSZ * CCH * HW];   // [b][c][m]
static __device__ float g_eatt[(size_t)BSZ * CCH * HW];   // [b][c][n]
static __device__ float g_colsum[BSZ * HW];               // sum over n  (for A1)
static __device__ float g_rowsum[BSZ * HW];               // sum over m  (for Bmat)
static __device__ float g_m1[BSZ * HW];
static __device__ float g_m2[BSZ * HW];

// ---------------- generic 128x128x8 fp32 GEMM mainloop ----------------
template <class LA, class LB>
__device__ __forceinline__ void gemm_loop(float (&acc)[8][8], int K, LA loadA, LB loadB,
                                          const float* As, const float* Bs, int ty, int tx)
{
    for (int kt = 0; kt < K; kt += BK) {
        loadA(kt);
        loadB(kt);
        __syncthreads();
#pragma unroll
        for (int kk = 0; kk < BK; ++kk) {
            float a[8];
#pragma unroll
            for (int i = 0; i < 8; ++i) a[i] = As[(ty * 8 + i) * ASTR + kk];
            float4 b0 = *reinterpret_cast<const float4*>(&Bs[kk * BN + tx * 8]);
            float4 b1 = *reinterpret_cast<const float4*>(&Bs[kk * BN + tx * 8 + 4]);
            float bb[8] = {b0.x, b0.y, b0.z, b0.w, b1.x, b1.y, b1.z, b1.w};
#pragma unroll
            for (int i = 0; i < 8; ++i)
#pragma unroll
                for (int j = 0; j < 8; ++j)
                    acc[i][j] = fmaf(a[i], bb[j], acc[i][j]);
        }
        __syncthreads();
    }
}

// ---------------- zero the softmax accumulators ----------------
__global__ void k_zero()
{
    int i = blockIdx.x * blockDim.x + threadIdx.x;
    if (i < BSZ * HW) { g_colsum[i] = 0.f; g_rowsum[i] = 0.f; }
}

// ---------------- GEMM1: ec_t[b][d][n] = sum_c We[d,c] * ex[b,c,n] ----------------
__global__ __launch_bounds__(NTHR) void k_gemm1(const float* __restrict__ in1,
                                                const float* __restrict__ We)
{
    __shared__ __align__(16) float smem[SMEMF];
    float* As = smem;
    float* Bs = smem + BM * ASTR;
    int tid = threadIdx.x, ty = tid >> 4, tx = tid & 15;
    int b = blockIdx.z;
    int m0 = blockIdx.y * BM;  // d
    int n0 = blockIdx.x * BN;  // n
    const float* Ap = We;                           // A[d,c], k-contig, lda=CCH
    const float* Bp = in1 + (size_t)b * CCH * HW;   // B[c,n], n-contig, ldn=HW
    float acc[8][8] = {};

    auto loadA = [&](int kt) {
#pragma unroll
        for (int r = 0; r < (BM * BK) / NTHR; ++r) {
            int idx = tid + r * NTHR;
            int mm = idx >> 3, kk = idx & 7;
            As[mm * ASTR + kk] = Ap[(size_t)(m0 + mm) * CCH + kt + kk];
        }
    };
    auto loadB = [&](int kt) {
#pragma unroll
        for (int r = 0; r < (BK * BN) / NTHR; ++r) {
            int idx = tid + r * NTHR;
            int nn = idx & (BN - 1), kk = idx >> 7;
            Bs[kk * BN + nn] = Bp[(size_t)(kt + kk) * HW + n0 + nn];
        }
    };
    gemm_loop(acc, CCH, loadA, loadB, As, Bs, ty, tx);

    float* Cp = g_ec + (size_t)b * CCH * HW;
#pragma unroll
    for (int i = 0; i < 8; ++i) {
        size_t off = (size_t)(m0 + ty * 8 + i) * HW + n0 + tx * 8;
        *reinterpret_cast<float4*>(&Cp[off])     = make_float4(acc[i][0], acc[i][1], acc[i][2], acc[i][3]);
        *reinterpret_cast<float4*>(&Cp[off + 4]) = make_float4(acc[i][4], acc[i][5], acc[i][6], acc[i][7]);
    }
}

// ---------------- GEMM2: E[b][n][m] = exp(sum_d ec[n,d] q[d,m]); accumulate row/col sums ----------------
__global__ __launch_bounds__(NTHR) void k_gemm2(const float* __restrict__ in2)
{
    __shared__ __align__(16) float smem[SMEMF];
    float* As = smem;
    float* Bs = smem + BM * ASTR;
    int tid = threadIdx.x, ty = tid >> 4, tx = tid & 15;
    int b = blockIdx.z;
    int m0 = blockIdx.y * BM;  // n (exemplar pixel, rows)
    int n0 = blockIdx.x * BN;  // m (query pixel, cols)
    const float* Ap = g_ec + (size_t)b * CCH * HW;  // A[n,d] = Ap[d*HW + n], m-contig
    const float* Bp = in2 + (size_t)b * CCH * HW;   // B[d,m], n-contig
    float acc[8][8] = {};

    auto loadA = [&](int kt) {
#pragma unroll
        for (int r = 0; r < (BM * BK) / NTHR; ++r) {
            int idx = tid + r * NTHR;
            int mm = idx & (BM - 1), kk = idx >> 7;
            As[mm * ASTR + kk] = Ap[(size_t)(kt + kk) * HW + m0 + mm];
        }
    };
    auto loadB = [&](int kt) {
#pragma unroll
        for (int r = 0; r < (BK * BN) / NTHR; ++r) {
            int idx = tid + r * NTHR;
            int nn = idx & (BN - 1), kk = idx >> 7;
            Bs[kk * BN + nn] = Bp[(size_t)(kt + kk) * HW + n0 + nn];
        }
    };
    gemm_loop(acc, CCH, loadA, loadB, As, Bs, ty, tx);

    // epilogue: exp, store E, reduce col/row sums
    float csum[8] = {}, rsum[8] = {};
    float* Eb = g_E + (size_t)b * HW * HW;
#pragma unroll
    for (int i = 0; i < 8; ++i) {
        float ev[8];
#pragma unroll
        for (int j = 0; j < 8; ++j) {
            ev[j] = expf(acc[i][j]);
            csum[j] += ev[j];
            rsum[i] += ev[j];
        }
        size_t off = (size_t)(m0 + ty * 8 + i) * HW + n0 + tx * 8;
        *reinterpret_cast<float4*>(&Eb[off])     = make_float4(ev[0], ev[1], ev[2], ev[3]);
        *reinterpret_cast<float4*>(&Eb[off + 4]) = make_float4(ev[4], ev[5], ev[6], ev[7]);
    }
    __syncthreads();
    float* red = smem;  // 16 x 128 reduction buffer (reuse tile smem)
#pragma unroll
    for (int j = 0; j < 8; ++j) red[ty * BN + tx * 8 + j] = csum[j];
    __syncthreads();
    if (tid < BN) {
        float s = 0.f;
#pragma unroll
        for (int t = 0; t < 16; ++t) s += red[t * BN + tid];
        atomicAdd(&g_colsum[b * HW + n0 + tid], s);
    }
    __syncthreads();
#pragma unroll
    for (int i = 0; i < 8; ++i) red[tx * BM + ty * 8 + i] = rsum[i];
    __syncthreads();
    if (tid < BM) {
        float s = 0.f;
#pragma unroll
        for (int t = 0; t < 16; ++t) s += red[t * BM + tid];
        atomicAdd(&g_rowsum[b * HW + m0 + tid], s);
    }
}

// ---------------- GEMM3: qatt[b][c][m] = (sum_n ex[c,n] E[n,m]) / colsum[m] ----------------
__global__ __launch_bounds__(NTHR) void k_gemm3(const float* __restrict__ in1)
{
    __shared__ __align__(16) float smem[SMEMF];
    float* As = smem;
    float* Bs = smem + BM * ASTR;
    int tid = threadIdx.x, ty = tid >> 4, tx = tid & 15;
    int b = blockIdx.z;
    int m0 = blockIdx.y * BM;  // c
    int n0 = blockIdx.x * BN;  // m
    const float* Ap = in1 + (size_t)b * CCH * HW;   // A[c,n], k-contig, lda=HW
    const float* Bp = g_E + (size_t)b * HW * HW;    // B[n,m], n-contig, ldn=HW
    float acc[8][8] = {};

    auto loadA = [&](int kt) {
#pragma unroll
        for (int r = 0; r < (BM * BK) / NTHR; ++r) {
            int idx = tid + r * NTHR;
            int mm = idx >> 3, kk = idx & 7;
            As[mm * ASTR + kk] = Ap[(size_t)(m0 + mm) * HW + kt + kk];
        }
    };
    auto loadB = [&](int kt) {
#pragma unroll
        for (int r = 0; r < (BK * BN) / NTHR; ++r) {
            int idx = tid + r * NTHR;
            int nn = idx & (BN - 1), kk = idx >> 7;
            Bs[kk * BN + nn] = Bp[(size_t)(kt + kk) * HW + n0 + nn];
        }
    };
    gemm_loop(acc, HW, loadA, loadB, As, Bs, ty, tx);

    float inv[8];
#pragma unroll
    for (int j = 0; j < 8; ++j) inv[j] = 1.0f / g_colsum[b * HW + n0 + tx * 8 + j];
    float* Cp = g_qatt + (size_t)b * CCH * HW;
#pragma unroll
    for (int i = 0; i < 8; ++i) {
        size_t off = (size_t)(m0 + ty * 8 + i) * HW + n0 + tx * 8;
        *reinterpret_cast<float4*>(&Cp[off])     = make_float4(acc[i][0]*inv[0], acc[i][1]*inv[1], acc[i][2]*inv[2], acc[i][3]*inv[3]);
        *reinterpret_cast<float4*>(&Cp[off + 4]) = make_float4(acc[i][4]*inv[4], acc[i][5]*inv[5], acc[i][6]*inv[6], acc[i][7]*inv[7]);
    }
}

// ---------------- GEMM4: eatt[b][c][n] = (sum_m q[c,m] E[n,m]) / rowsum[n] ----------------
__global__ __launch_bounds__(NTHR) void k_gemm4(const float* __restrict__ in2)
{
    __shared__ __align__(16) float smem[SMEMF];
    float* As = smem;
    float* Bs = smem + BM * ASTR;
    int tid = threadIdx.x, ty = tid >> 4, tx = tid & 15;
    int b = blockIdx.z;
    int m0 = blockIdx.y * BM;  // c
    int n0 = blockIdx.x * BN;  // n
    const float* Ap = in2 + (size_t)b * CCH * HW;   // A[c,m], k-contig, lda=HW
    const float* Eb = g_E + (size_t)b * HW * HW;    // B[k=m, n] = Eb[n*HW + m], k-contig
    float acc[8][8] = {};

    auto loadA = [&](int kt) {
#pragma unroll
        for (int r = 0; r < (BM * BK) / NTHR; ++r) {
            int idx = tid + r * NTHR;
            int mm = idx >> 3, kk = idx & 7;
            As[mm * ASTR + kk] = Ap[(size_t)(m0 + mm) * HW + kt + kk];
        }
    };
    auto loadB = [&](int kt) {
#pragma unroll
        for (int r = 0; r < (BK * BN) / NTHR; ++r) {
            int idx = tid + r * NTHR;
            int kk = idx & 7, nn = idx >> 3;
            Bs[kk * BN + nn] = Eb[(size_t)(n0 + nn) * HW + kt + kk];
        }
    };
    gemm_loop(acc, HW, loadA, loadB, As, Bs, ty, tx);

    float inv[8];
#pragma unroll
    for (int j = 0; j < 8; ++j) inv[j] = 1.0f / g_rowsum[b * HW + n0 + tx * 8 + j];
    float* Cp = g_eatt + (size_t)b * CCH * HW;
#pragma unroll
    for (int i = 0; i < 8; ++i) {
        size_t off = (size_t)(m0 + ty * 8 + i) * HW + n0 + tx * 8;
        *reinterpret_cast<float4*>(&Cp[off])     = make_float4(acc[i][0]*inv[0], acc[i][1]*inv[1], acc[i][2]*inv[2], acc[i][3]*inv[3]);
        *reinterpret_cast<float4*>(&Cp[off + 4]) = make_float4(acc[i][4]*inv[4], acc[i][5]*inv[5], acc[i][6]*inv[6], acc[i][7]*inv[7]);
    }
}

// ---------------- gates: m1 = sigmoid(gate_w . eatt[:,x]), m2 = sigmoid(gate_w . qatt[:,x]) ----------------
__global__ void k_gate(const float* __restrict__ gw)
{
    __shared__ float sg[CCH];
    int tid = threadIdx.x;
    sg[tid] = gw[tid];  // blockDim == CCH == 256
    __syncthreads();
    int b = blockIdx.y;
    int x = blockIdx.x * 256 + tid;
    const float* e = g_eatt + (size_t)b * CCH * HW + x;
    const float* qa = g_qatt + (size_t)b * CCH * HW + x;
    float a1 = 0.f, a2 = 0.f;
#pragma unroll 4
    for (int c = 0; c < CCH; ++c) {
        float w = sg[c];
        a1 = fmaf(e[(size_t)c * HW], w, a1);
        a2 = fmaf(qa[(size_t)c * HW], w, a2);
    }
    g_m1[b * HW + x] = 1.f / (1.f + expf(-a1));
    g_m2[b * HW + x] = 1.f / (1.f + expf(-a2));
}

// ---------------- final 1x1 conv on concat: out[b][o][x] = sum_k W[o,k] * B[k,x] ----------------
// B[k,x] = k < C ? att[k,x]*mg[x] : inp[k-C,x]
__global__ __launch_bounds__(NTHR) void k_conv(const float* __restrict__ W,
                                               const float* __restrict__ inp,
                                               float* __restrict__ out, int which)
{
    __shared__ __align__(16) float smem[SMEMF];
    float* As = smem;
    float* Bs = smem + BM * ASTR;
    int tid = threadIdx.x, ty = tid >> 4, tx = tid & 15;
    int b = blockIdx.z;
    int m0 = blockIdx.y * BM;  // o
    int n0 = blockIdx.x * BN;  // x
    const float* attb = (which ? g_qatt : g_eatt) + (size_t)b * CCH * HW;
    const float* mb = (which ? g_m2 : g_m1) + (size_t)b * HW;
    const float* inpb = inp + (size_t)b * CCH * HW;
    float acc[8][8] = {};

    auto loadA = [&](int kt) {
#pragma unroll
        for (int r = 0; r < (BM * BK) / NTHR; ++r) {
            int idx = tid + r * NTHR;
            int mm = idx >> 3, kk = idx & 7;
            As[mm * ASTR + kk] = W[(size_t)(m0 + mm) * (2 * CCH) + kt + kk];
        }
    };
    auto loadB = [&](int kt) {
#pragma unroll
        for (int r = 0; r < (BK * BN) / NTHR; ++r) {
            int idx = tid + r * NTHR;
            int nn = idx & (BN - 1), kk = idx >> 7;
            int k = kt + kk, n = n0 + nn;
            float v;
            if (k < CCH) v = attb[(size_t)k * HW + n] * mb[n];
            else         v = inpb[(size_t)(k - CCH) * HW + n];
            Bs[kk * BN + nn] = v;
        }
    };
    gemm_loop(acc, 2 * CCH, loadA, loadB, As, Bs, ty, tx);

#pragma unroll
    for (int i = 0; i < 8; ++i) {
        size_t off = (size_t)b * CCH * HW + (size_t)(m0 + ty * 8 + i) * HW + n0 + tx * 8;
        *reinterpret_cast<float4*>(&out[off])     = make_float4(acc[i][0], acc[i][1], acc[i][2], acc[i][3]);
        *reinterpret_cast<float4*>(&out[off + 4]) = make_float4(acc[i][4], acc[i][5], acc[i][6], acc[i][7]);
    }
}

extern "C" void kernel_launch(void* const* d_in, const int* in_sizes, int n_in,
                              void* d_out, int out_size)
{
    const float* in1 = (const float*)d_in[0];
    const float* in2 = (const float*)d_in[1];
    const float* We  = (const float*)d_in[2];
    const float* gw  = (const float*)d_in[3];
    const float* W1  = (const float*)d_in[4];
    const float* W2  = (const float*)d_in[5];
    float* out = (float*)d_out;

    dim3 blk(NTHR);
    k_zero<<<(BSZ * HW + 255) / 256, 256>>>();
    k_gemm1<<<dim3(HW / BN, CCH / BM, BSZ), blk>>>(in1, We);
    k_gemm2<<<dim3(HW / BN, HW / BM, BSZ), blk>>>(in2);
    k_gemm3<<<dim3(HW / BN, CCH / BM, BSZ), blk>>>(in1);
    k_gemm4<<<dim3(HW / BN, CCH / BM, BSZ), blk>>>(in2);
    k_gate<<<dim3(HW / 256, BSZ), 256>>>(gw);
    k_conv<<<dim3(HW / BN, CCH / BM, BSZ), blk>>>(W1, in1, out, 0);
    k_conv<<<dim3(HW / BN, CCH / BM, BSZ), blk>>>(W2, in2, out + (size_t)BSZ * CCH * HW, 1);
}

// round 2
// speedup vs baseline: 1.0551x; 1.0551x over previous
#include <cuda_runtime.h>
#include <math.h>

#define BSZ 4
#define CCH 256
#define HW  4096

#define BM 128
#define BN 128
#define BK 8
#define ASTR (BK + 1)
#define NTHR 256
#define SMEMF (BM * ASTR + BK * BN) /* 1152 + 1024 = 2176 floats */

// ---------------- scratch (no cudaMalloc allowed) ----------------
static __device__ float g_ec[(size_t)BSZ * CCH * HW];     // [b][d][n] 16MB
static __device__ float g_E[(size_t)BSZ * HW * HW];       // [b][n][m] 268MB
static __device__ float g_qatt[(size_t)BSZ * CCH * HW];   // [b][c][m]
static __device__ float g_eatt[(size_t)BSZ * CCH * HW];   // [b][c][n]
static __device__ float g_colsum[BSZ * HW];               // sum over n  (for A1)
static __device__ float g_rowsum[BSZ * HW];               // sum over m  (for Bmat)
static __device__ float g_m1[BSZ * HW];
static __device__ float g_m2[BSZ * HW];

// ---------------- generic 128x128x8 fp32 GEMM mainloop ----------------
template <class LA, class LB>
__device__ __forceinline__ void gemm_loop(float (&acc)[8][8], int K, LA loadA, LB loadB,
                                          const float* As, const float* Bs, int ty, int tx)
{
    for (int kt = 0; kt < K; kt += BK) {
        loadA(kt);
        loadB(kt);
        __syncthreads();
#pragma unroll
        for (int kk = 0; kk < BK; ++kk) {
            float a[8];
#pragma unroll
            for (int i = 0; i < 8; ++i) a[i] = As[(ty * 8 + i) * ASTR + kk];
            float4 b0 = *reinterpret_cast<const float4*>(&Bs[kk * BN + tx * 8]);
            float4 b1 = *reinterpret_cast<const float4*>(&Bs[kk * BN + tx * 8 + 4]);
            float bb[8] = {b0.x, b0.y, b0.z, b0.w, b1.x, b1.y, b1.z, b1.w};
#pragma unroll
            for (int i = 0; i < 8; ++i)
#pragma unroll
                for (int j = 0; j < 8; ++j)
                    acc[i][j] = fmaf(a[i], bb[j], acc[i][j]);
        }
        __syncthreads();
    }
}

// ---------------- zero the softmax accumulators ----------------
__global__ void k_zero()
{
    int i = blockIdx.x * blockDim.x + threadIdx.x;
    if (i < BSZ * HW) { g_colsum[i] = 0.f; g_rowsum[i] = 0.f; }
}

// ---------------- GEMM1: ec_t[b][d][n] = sum_c We[d,c] * ex[b,c,n] ----------------
__global__ __launch_bounds__(NTHR) void k_gemm1(const float* __restrict__ in1,
                                                const float* __restrict__ We)
{
    __shared__ __align__(16) float smem[SMEMF];
    float* As = smem;
    float* Bs = smem + BM * ASTR;
    int tid = threadIdx.x, ty = tid >> 4, tx = tid & 15;
    int b = blockIdx.z;
    int m0 = blockIdx.y * BM;  // d
    int n0 = blockIdx.x * BN;  // n
    const float* Ap = We;                           // A[d,c], k-contig, lda=CCH
    const float* Bp = in1 + (size_t)b * CCH * HW;   // B[c,n], n-contig, ldn=HW
    float acc[8][8] = {};

    auto loadA = [&](int kt) {
#pragma unroll
        for (int r = 0; r < (BM * BK) / NTHR; ++r) {
            int idx = tid + r * NTHR;
            int mm = idx >> 3, kk = idx & 7;
            As[mm * ASTR + kk] = Ap[(size_t)(m0 + mm) * CCH + kt + kk];
        }
    };
    auto loadB = [&](int kt) {
#pragma unroll
        for (int r = 0; r < (BK * BN) / NTHR; ++r) {
            int idx = tid + r * NTHR;
            int nn = idx & (BN - 1), kk = idx >> 7;
            Bs[kk * BN + nn] = Bp[(size_t)(kt + kk) * HW + n0 + nn];
        }
    };
    gemm_loop(acc, CCH, loadA, loadB, As, Bs, ty, tx);

    float* Cp = g_ec + (size_t)b * CCH * HW;
#pragma unroll
    for (int i = 0; i < 8; ++i) {
        size_t off = (size_t)(m0 + ty * 8 + i) * HW + n0 + tx * 8;
        *reinterpret_cast<float4*>(&Cp[off])     = make_float4(acc[i][0], acc[i][1], acc[i][2], acc[i][3]);
        *reinterpret_cast<float4*>(&Cp[off + 4]) = make_float4(acc[i][4], acc[i][5], acc[i][6], acc[i][7]);
    }
}

// ---------------- GEMM2: E[b][n][m] = exp(sum_d ec[n,d] q[d,m]); accumulate row/col sums ----------------
__global__ __launch_bounds__(NTHR) void k_gemm2(const float* __restrict__ in2)
{
    __shared__ __align__(16) float smem[SMEMF];
    float* As = smem;
    float* Bs = smem + BM * ASTR;
    int tid = threadIdx.x, ty = tid >> 4, tx = tid & 15;
    int b = blockIdx.z;
    int m0 = blockIdx.y * BM;  // n (exemplar pixel, rows)
    int n0 = blockIdx.x * BN;  // m (query pixel, cols)
    const float* Ap = g_ec + (size_t)b * CCH * HW;  // A[n,d] = Ap[d*HW + n], m-contig
    const float* Bp = in2 + (size_t)b * CCH * HW;   // B[d,m], n-contig
    float acc[8][8] = {};

    auto loadA = [&](int kt) {
#pragma unroll
        for (int r = 0; r < (BM * BK) / NTHR; ++r) {
            int idx = tid + r * NTHR;
            int mm = idx & (BM - 1), kk = idx >> 7;
            As[mm * ASTR + kk] = Ap[(size_t)(kt + kk) * HW + m0 + mm];
        }
    };
    auto loadB = [&](int kt) {
#pragma unroll
        for (int r = 0; r < (BK * BN) / NTHR; ++r) {
            int idx = tid + r * NTHR;
            int nn = idx & (BN - 1), kk = idx >> 7;
            Bs[kk * BN + nn] = Bp[(size_t)(kt + kk) * HW + n0 + nn];
        }
    };
    gemm_loop(acc, CCH, loadA, loadB, As, Bs, ty, tx);

    // epilogue: exp, store E, reduce col/row sums
    float csum[8] = {}, rsum[8] = {};
    float* Eb = g_E + (size_t)b * HW * HW;
#pragma unroll
    for (int i = 0; i < 8; ++i) {
        float ev[8];
#pragma unroll
        for (int j = 0; j < 8; ++j) {
            ev[j] = expf(acc[i][j]);
            csum[j] += ev[j];
            rsum[i] += ev[j];
        }
        size_t off = (size_t)(m0 + ty * 8 + i) * HW + n0 + tx * 8;
        *reinterpret_cast<float4*>(&Eb[off])     = make_float4(ev[0], ev[1], ev[2], ev[3]);
        *reinterpret_cast<float4*>(&Eb[off + 4]) = make_float4(ev[4], ev[5], ev[6], ev[7]);
    }
    __syncthreads();
    float* red = smem;  // 16 x 128 reduction buffer (reuse tile smem)
#pragma unroll
    for (int j = 0; j < 8; ++j) red[ty * BN + tx * 8 + j] = csum[j];
    __syncthreads();
    if (tid < BN) {
        float s = 0.f;
#pragma unroll
        for (int t = 0; t < 16; ++t) s += red[t * BN + tid];
        atomicAdd(&g_colsum[b * HW + n0 + tid], s);
    }
    __syncthreads();
#pragma unroll
    for (int i = 0; i < 8; ++i) red[tx * BM + ty * 8 + i] = rsum[i];
    __syncthreads();
    if (tid < BM) {
        float s = 0.f;
#pragma unroll
        for (int t = 0; t < 16; ++t) s += red[t * BM + tid];
        atomicAdd(&g_rowsum[b * HW + m0 + tid], s);
    }
}

// ---------------- GEMM3: qatt[b][c][m] = (sum_n ex[c,n] E[n,m]) / colsum[m] ----------------
__global__ __launch_bounds__(NTHR) void k_gemm3(const float* __restrict__ in1)
{
    __shared__ __align__(16) float smem[SMEMF];
    float* As = smem;
    float* Bs = smem + BM * ASTR;
    int tid = threadIdx.x, ty = tid >> 4, tx = tid & 15;
    int b = blockIdx.z;
    int m0 = blockIdx.y * BM;  // c
    int n0 = blockIdx.x * BN;  // m
    const float* Ap = in1 + (size_t)b * CCH * HW;   // A[c,n], k-contig, lda=HW
    const float* Bp = g_E + (size_t)b * HW * HW;    // B[n,m], n-contig, ldn=HW
    float acc[8][8] = {};

    auto loadA = [&](int kt) {
#pragma unroll
        for (int r = 0; r < (BM * BK) / NTHR; ++r) {
            int idx = tid + r * NTHR;
            int mm = idx >> 3, kk = idx & 7;
            As[mm * ASTR + kk] = Ap[(size_t)(m0 + mm) * HW + kt + kk];
        }
    };
    auto loadB = [&](int kt) {
#pragma unroll
        for (int r = 0; r < (BK * BN) / NTHR; ++r) {
            int idx = tid + r * NTHR;
            int nn = idx & (BN - 1), kk = idx >> 7;
            Bs[kk * BN + nn] = Bp[(size_t)(kt + kk) * HW + n0 + nn];
        }
    };
    gemm_loop(acc, HW, loadA, loadB, As, Bs, ty, tx);

    float inv[8];
#pragma unroll
    for (int j = 0; j < 8; ++j) inv[j] = 1.0f / g_colsum[b * HW + n0 + tx * 8 + j];
    float* Cp = g_qatt + (size_t)b * CCH * HW;
#pragma unroll
    for (int i = 0; i < 8; ++i) {
        size_t off = (size_t)(m0 + ty * 8 + i) * HW + n0 + tx * 8;
        *reinterpret_cast<float4*>(&Cp[off])     = make_float4(acc[i][0]*inv[0], acc[i][1]*inv[1], acc[i][2]*inv[2], acc[i][3]*inv[3]);
        *reinterpret_cast<float4*>(&Cp[off + 4]) = make_float4(acc[i][4]*inv[4], acc[i][5]*inv[5], acc[i][6]*inv[6], acc[i][7]*inv[7]);
    }
}

// ---------------- GEMM4: eatt[b][c][n] = (sum_m q[c,m] E[n,m]) / rowsum[n] ----------------
__global__ __launch_bounds__(NTHR) void k_gemm4(const float* __restrict__ in2)
{
    __shared__ __align__(16) float smem[SMEMF];
    float* As = smem;
    float* Bs = smem + BM * ASTR;
    int tid = threadIdx.x, ty = tid >> 4, tx = tid & 15;
    int b = blockIdx.z;
    int m0 = blockIdx.y * BM;  // c
    int n0 = blockIdx.x * BN;  // n
    const float* Ap = in2 + (size_t)b * CCH * HW;   // A[c,m], k-contig, lda=HW
    const float* Eb = g_E + (size_t)b * HW * HW;    // B[k=m, n] = Eb[n*HW + m], k-contig
    float acc[8][8] = {};

    auto loadA = [&](int kt) {
#pragma unroll
        for (int r = 0; r < (BM * BK) / NTHR; ++r) {
            int idx = tid + r * NTHR;
            int mm = idx >> 3, kk = idx & 7;
            As[mm * ASTR + kk] = Ap[(size_t)(m0 + mm) * HW + kt + kk];
        }
    };
    auto loadB = [&](int kt) {
#pragma unroll
        for (int r = 0; r < (BK * BN) / NTHR; ++r) {
            int idx = tid + r * NTHR;
            int kk = idx & 7, nn = idx >> 3;
            Bs[kk * BN + nn] = Eb[(size_t)(n0 + nn) * HW + kt + kk];
        }
    };
    gemm_loop(acc, HW, loadA, loadB, As, Bs, ty, tx);

    float inv[8];
#pragma unroll
    for (int j = 0; j < 8; ++j) inv[j] = 1.0f / g_rowsum[b * HW + n0 + tx * 8 + j];
    float* Cp = g_eatt + (size_t)b * CCH * HW;
#pragma unroll
    for (int i = 0; i < 8; ++i) {
        size_t off = (size_t)(m0 + ty * 8 + i) * HW + n0 + tx * 8;
        *reinterpret_cast<float4*>(&Cp[off])     = make_float4(acc[i][0]*inv[0], acc[i][1]*inv[1], acc[i][2]*inv[2], acc[i][3]*inv[3]);
        *reinterpret_cast<float4*>(&Cp[off + 4]) = make_float4(acc[i][4]*inv[4], acc[i][5]*inv[5], acc[i][6]*inv[6], acc[i][7]*inv[7]);
    }
}

// ---------------- gates: m1 = sigmoid(gate_w . eatt[:,x]), m2 = sigmoid(gate_w . qatt[:,x]) ----------------
__global__ void k_gate(const float* __restrict__ gw)
{
    __shared__ float sg[CCH];
    int tid = threadIdx.x;
    sg[tid] = gw[tid];  // blockDim == CCH == 256
    __syncthreads();
    int b = blockIdx.y;
    int x = blockIdx.x * 256 + tid;
    const float* e = g_eatt + (size_t)b * CCH * HW + x;
    const float* qa = g_qatt + (size_t)b * CCH * HW + x;
    float a1 = 0.f, a2 = 0.f;
#pragma unroll 4
    for (int c = 0; c < CCH; ++c) {
        float w = sg[c];
        a1 = fmaf(e[(size_t)c * HW], w, a1);
        a2 = fmaf(qa[(size_t)c * HW], w, a2);
    }
    g_m1[b * HW + x] = 1.f / (1.f + expf(-a1));
    g_m2[b * HW + x] = 1.f / (1.f + expf(-a2));
}

// ---------------- final 1x1 conv on concat: out[b][o][x] = sum_k W[o,k] * B[k,x] ----------------
// B[k,x] = k < C ? att[k,x]*mg[x] : inp[k-C,x]
__global__ __launch_bounds__(NTHR) void k_conv(const float* __restrict__ W,
                                               const float* __restrict__ inp,
                                               float* __restrict__ out, int which)
{
    __shared__ __align__(16) float smem[SMEMF];
    float* As = smem;
    float* Bs = smem + BM * ASTR;
    int tid = threadIdx.x, ty = tid >> 4, tx = tid & 15;
    int b = blockIdx.z;
    int m0 = blockIdx.y * BM;  // o
    int n0 = blockIdx.x * BN;  // x
    const float* attb = (which ? g_qatt : g_eatt) + (size_t)b * CCH * HW;
    const float* mb = (which ? g_m2 : g_m1) + (size_t)b * HW;
    const float* inpb = inp + (size_t)b * CCH * HW;
    float acc[8][8] = {};

    auto loadA = [&](int kt) {
#pragma unroll
        for (int r = 0; r < (BM * BK) / NTHR; ++r) {
            int idx = tid + r * NTHR;
            int mm = idx >> 3, kk = idx & 7;
            As[mm * ASTR + kk] = W[(size_t)(m0 + mm) * (2 * CCH) + kt + kk];
        }
    };
    auto loadB = [&](int kt) {
#pragma unroll
        for (int r = 0; r < (BK * BN) / NTHR; ++r) {
            int idx = tid + r * NTHR;
            int nn = idx & (BN - 1), kk = idx >> 7;
            int k = kt + kk, n = n0 + nn;
            float v;
            if (k < CCH) v = attb[(size_t)k * HW + n] * mb[n];
            else         v = inpb[(size_t)(k - CCH) * HW + n];
            Bs[kk * BN + nn] = v;
        }
    };
    gemm_loop(acc, 2 * CCH, loadA, loadB, As, Bs, ty, tx);

#pragma unroll
    for (int i = 0; i < 8; ++i) {
        size_t off = (size_t)b * CCH * HW + (size_t)(m0 + ty * 8 + i) * HW + n0 + tx * 8;
        *reinterpret_cast<float4*>(&out[off])     = make_float4(acc[i][0], acc[i][1], acc[i][2], acc[i][3]);
        *reinterpret_cast<float4*>(&out[off + 4]) = make_float4(acc[i][4], acc[i][5], acc[i][6], acc[i][7]);
    }
}

extern "C" void kernel_launch(void* const* d_in, const int* in_sizes, int n_in,
                              void* d_out, int out_size)
{
    const float* in1 = (const float*)d_in[0];
    const float* in2 = (const float*)d_in[1];
    const float* We  = (const float*)d_in[2];
    const float* gw  = (const float*)d_in[3];
    const float* W1  = (const float*)d_in[4];
    const float* W2  = (const float*)d_in[5];
    float* out = (float*)d_out;

    dim3 blk(NTHR);
    k_zero<<<(BSZ * HW + 255) / 256, 256>>>();
    k_gemm1<<<dim3(HW / BN, CCH / BM, BSZ), blk>>>(in1, We);
    k_gemm2<<<dim3(HW / BN, HW / BM, BSZ), blk>>>(in2);
    k_gemm3<<<dim3(HW / BN, CCH / BM, BSZ), blk>>>(in1);
    k_gemm4<<<dim3(HW / BN, CCH / BM, BSZ), blk>>>(in2);
    k_gate<<<dim3(HW / 256, BSZ), 256>>>(gw);
    k_conv<<<dim3(HW / BN, CCH / BM, BSZ), blk>>>(W1, in1, out, 0);
    k_conv<<<dim3(HW / BN, CCH / BM, BSZ), blk>>>(W2, in2, out + (size_t)BSZ * CCH * HW, 1);
}

// round 7
// speedup vs baseline: 2.1674x; 2.0541x over previous
#include <cuda_runtime.h>
#include <cuda_bf16.h>
#include <mma.h>
#include <cstdint>
#include <math.h>

using namespace nvcuda;

#define NB 4
#define CCH 256
#define HW 4096

#define LDT 40                  /* smem tile row stride, elements */
#define TILEB (128 * LDT * 2)   /* 10240 B */
#define SM_GEMM (4 * TILEB)     /* 40960 B */

typedef wmma::fragment<wmma::matrix_a, 16, 16, 16, __nv_bfloat16, wmma::row_major> FragA;
typedef wmma::fragment<wmma::matrix_b, 16, 16, 16, __nv_bfloat16, wmma::col_major> FragB;
typedef wmma::fragment<wmma::accumulator, 16, 16, 16, float> FragC;

/* ---------------- scratch (no cudaMalloc allowed) ---------------- */
#define SZ_CN ((size_t)NB * CCH * HW)
#define SZ_EE ((size_t)NB * HW * HW)
static __device__ __align__(16) __nv_bfloat16 g_ex_h[SZ_CN], g_ex_l[SZ_CN];   /* in1 [b][c][n] */
static __device__ __align__(16) __nv_bfloat16 g_q_h[SZ_CN],  g_q_l[SZ_CN];    /* in2 [b][c][m] */
static __device__ __align__(16) __nv_bfloat16 g_ext_h[SZ_CN], g_ext_l[SZ_CN]; /* in1^T [b][x][c] */
static __device__ __align__(16) __nv_bfloat16 g_qt_h[SZ_CN],  g_qt_l[SZ_CN];  /* in2^T [b][x][c] */
static __device__ __align__(16) __nv_bfloat16 g_We_h[CCH*CCH], g_We_l[CCH*CCH];
static __device__ __align__(16) __nv_bfloat16 g_W1_h[CCH*2*CCH], g_W1_l[CCH*2*CCH];
static __device__ __align__(16) __nv_bfloat16 g_W2_h[CCH*2*CCH], g_W2_l[CCH*2*CCH];
static __device__ __align__(16) __nv_bfloat16 g_ec_h[SZ_CN], g_ec_l[SZ_CN];   /* [b][n][d] */
static __device__ __align__(16) __nv_bfloat16 g_En_h[SZ_EE], g_En_l[SZ_EE];   /* E [b][n][m] */
static __device__ __align__(16) __nv_bfloat16 g_Em_h[SZ_EE], g_Em_l[SZ_EE];   /* E^T [b][m][n] */
static __device__ __align__(16) __nv_bfloat16 g_qatt_h[SZ_CN], g_qatt_l[SZ_CN]; /* gated [b][m][c] */
static __device__ __align__(16) __nv_bfloat16 g_eatt_h[SZ_CN], g_eatt_l[SZ_CN]; /* gated [b][n][c] */
static __device__ __align__(16) float g_AF[SZ_EE];     /* raw logits */
static __device__ __align__(16) float g_ecF[SZ_CN];
static __device__ __align__(16) float g_qattF[SZ_CN], g_eattF[SZ_CN];
static __device__ float g_colsum[NB*HW], g_rowsum[NB*HW];

/* ============ wmma 128x128 GEMM core: 3-pass split-bf16, reg-staged double buffer ============ */
/* C[r][c] = sum over passes of Apass[r][k] * Bpass[c][k]; A,B tiles k-major in smem.          */
__device__ void gemm_core(char* sm,
    const __nv_bfloat16* Ah, const __nv_bfloat16* Al, int lda,
    const __nv_bfloat16* B1h, const __nv_bfloat16* B1l,
    const __nv_bfloat16* B2h, const __nv_bfloat16* B2l, int ksplit, int ldb,
    int K, FragC (&acc)[2][4])
{
    const int t = threadIdx.x, wid = t >> 5;
    const int wm = wid >> 1, wn = wid & 1;  /* 4x2 warps: 32-row x 64-col per warp */
    const int nch = K / 32, total = nch * 3;

#pragma unroll
    for (int mf = 0; mf < 2; ++mf)
#pragma unroll
        for (int nf = 0; nf < 4; ++nf)
            wmma::fill_fragment(acc[mf][nf], 0.0f);

    auto src = [&](int it, const __nv_bfloat16*& A, const __nv_bfloat16*& B) {
        int p = it / nch, k0 = (it - p * nch) * 32;
        A = ((p == 2) ? Al : Ah) + k0;
        const __nv_bfloat16* bh = B1h; const __nv_bfloat16* bl = B1l; int kb = k0;
        if (k0 >= ksplit) { bh = B2h; bl = B2l; kb = k0 - ksplit; }
        B = ((p == 1) ? bl : bh) + kb;
    };
    auto g2r = [&](const __nv_bfloat16* A, const __nv_bfloat16* B, uint4* ra, uint4* rb) {
#pragma unroll
        for (int i = 0; i < 2; ++i) {
            int v = t * 2 + i, r = v >> 2, c = v & 3;
            ra[i] = *(const uint4*)(A + (size_t)r * lda + c * 8);
            rb[i] = *(const uint4*)(B + (size_t)r * ldb + c * 8);
        }
    };
    auto r2s = [&](int buf, const uint4* ra, const uint4* rb) {
#pragma unroll
        for (int i = 0; i < 2; ++i) {
            int v = t * 2 + i, r = v >> 2, c = v & 3;
            *(uint4*)(sm + buf * TILEB + r * (LDT * 2) + c * 16) = ra[i];
            *(uint4*)(sm + 2 * TILEB + buf * TILEB + r * (LDT * 2) + c * 16) = rb[i];
        }
    };
    auto comp = [&](int buf) {
        const __nv_bfloat16* As = (const __nv_bfloat16*)(sm + buf * TILEB);
        const __nv_bfloat16* Bs = (const __nv_bfloat16*)(sm + 2 * TILEB + buf * TILEB);
#pragma unroll
        for (int kk = 0; kk < 32; kk += 16) {
            FragA af[2]; FragB bfr[4];
#pragma unroll
            for (int mf = 0; mf < 2; ++mf)
                wmma::load_matrix_sync(af[mf], As + (wm * 32 + mf * 16) * LDT + kk, LDT);
#pragma unroll
            for (int nf = 0; nf < 4; ++nf)
                wmma::load_matrix_sync(bfr[nf], Bs + (wn * 64 + nf * 16) * LDT + kk, LDT);
#pragma unroll
            for (int mf = 0; mf < 2; ++mf)
#pragma unroll
                for (int nf = 0; nf < 4; ++nf)
                    wmma::mma_sync(acc[mf][nf], af[mf], bfr[nf], acc[mf][nf]);
        }
    };

    const __nv_bfloat16 *A, *B;
    uint4 ra[2], rb[2];
    src(0, A, B);
    g2r(A, B, ra, rb);
    r2s(0, ra, rb);
    __syncthreads();
    for (int it = 0; it < total; ++it) {
        bool more = (it + 1 < total);
        if (more) { src(it + 1, A, B); g2r(A, B, ra, rb); }
        comp(it & 1);
        if (more) r2s((it + 1) & 1, ra, rb);
        __syncthreads();
    }
}

__device__ __forceinline__ void store_c(FragC (&acc)[2][4], float* C, int ldc)
{
    int wid = threadIdx.x >> 5, wm = wid >> 1, wn = wid & 1;
#pragma unroll
    for (int mf = 0; mf < 2; ++mf)
#pragma unroll
        for (int nf = 0; nf < 4; ++nf)
            wmma::store_matrix_sync(C + (size_t)(wm * 32 + mf * 16) * ldc + wn * 64 + nf * 16,
                                    acc[mf][nf], ldc, wmma::mem_row_major);
}

/* ---------------- GEMM1: ecF[n][d] = ext[n][:] . We[d][:] ---------------- */
__global__ __launch_bounds__(256) void k_g1()
{
    extern __shared__ __align__(128) char sm[];
    int b = blockIdx.z, r0 = blockIdx.y * 128, c0 = blockIdx.x * 128;
    FragC acc[2][4];
    size_t ao = ((size_t)b * HW + r0) * CCH;
    gemm_core(sm, g_ext_h + ao, g_ext_l + ao, CCH,
              g_We_h + (size_t)c0 * CCH, g_We_l + (size_t)c0 * CCH,
              g_We_h + (size_t)c0 * CCH, g_We_l + (size_t)c0 * CCH, 1 << 30, CCH, CCH, acc);
    store_c(acc, g_ecF + ao + c0, CCH);
}

/* ---------------- GEMM2: AF[n][m] = ec[n][:] . qt[m][:] (raw logits) ---------------- */
__global__ __launch_bounds__(256) void k_g2()
{
    extern __shared__ __align__(128) char sm[];
    int b = blockIdx.z, r0 = blockIdx.y * 128, c0 = blockIdx.x * 128;
    FragC acc[2][4];
    size_t ao = ((size_t)b * HW + r0) * CCH, bo = ((size_t)b * HW + c0) * CCH;
    gemm_core(sm, g_ec_h + ao, g_ec_l + ao, CCH,
              g_qt_h + bo, g_qt_l + bo, g_qt_h + bo, g_qt_l + bo, 1 << 30, CCH, CCH, acc);
    store_c(acc, g_AF + ((size_t)b * HW + r0) * HW + c0, HW);
}

/* ---------------- GEMM3/4: attF[x][c] = E_x[:] . inp[c][:] (raw) ---------------- */
__global__ __launch_bounds__(256) void k_att(int sel)
{
    extern __shared__ __align__(128) char sm[];
    int b = blockIdx.z, r0 = blockIdx.y * 128, c0 = blockIdx.x * 128;
    const __nv_bfloat16 *Ah, *Al, *Bh, *Bl; float* Cf;
    if (sel == 0) { Ah = g_Em_h; Al = g_Em_l; Bh = g_ex_h; Bl = g_ex_l; Cf = g_qattF; }
    else          { Ah = g_En_h; Al = g_En_l; Bh = g_q_h;  Bl = g_q_l;  Cf = g_eattF; }
    FragC acc[2][4];
    size_t ao = ((size_t)b * HW + r0) * HW, bo = ((size_t)b * CCH + c0) * HW;
    gemm_core(sm, Ah + ao, Al + ao, HW, Bh + bo, Bl + bo, Bh + bo, Bl + bo, 1 << 30, HW, HW, acc);
    store_c(acc, Cf + ((size_t)b * HW + r0) * CCH + c0, CCH);
}

/* ---------------- conv: out[o][x] = W[o][0:512] . [att | inp_t][x][0:512] ---------------- */
__global__ __launch_bounds__(256) void k_conv(float* __restrict__ out, int w)
{
    extern __shared__ __align__(128) char sm[];
    int b = blockIdx.z, o0 = blockIdx.y * 128, x0 = blockIdx.x * 128;
    const __nv_bfloat16 *Wh, *Wl, *B1h, *B1l, *B2h, *B2l;
    if (w == 0) { Wh = g_W1_h; Wl = g_W1_l; B1h = g_eatt_h; B1l = g_eatt_l; B2h = g_ext_h; B2l = g_ext_l; }
    else        { Wh = g_W2_h; Wl = g_W2_l; B1h = g_qatt_h; B1l = g_qatt_l; B2h = g_qt_h;  B2l = g_qt_l; }
    FragC acc[2][4];
    size_t bo = ((size_t)b * HW + x0) * CCH;
    gemm_core(sm, Wh + (size_t)o0 * 512, Wl + (size_t)o0 * 512, 512,
              B1h + bo, B1l + bo, B2h + bo, B2l + bo, 256, CCH, 512, acc);
    store_c(acc, out + ((size_t)b * CCH + o0) * HW + x0, HW);
}

/* ---------------- ew2: e=exp(AF); En/Em hi-lo; row/col sums ---------------- */
__global__ __launch_bounds__(256) void k_ew2()
{
    __shared__ float te[64][33];   /* [m_local][n_local] */
    __shared__ float sc[8][64];
    int b = blockIdx.z, n0 = blockIdx.y * 32, m0 = blockIdx.x * 64;
    int x = threadIdx.x, y = threadIdx.y;  /* block (32,8) */
    const float* src = g_AF + ((size_t)b * HW + n0) * HW + m0;
    float rsum[4]; float cs0 = 0.f, cs1 = 0.f;
#pragma unroll
    for (int i = 0; i < 4; ++i) {
        int n = y + i * 8;
        float2 v = *(const float2*)(src + (size_t)n * HW + 2 * x);
        float e0 = expf(v.x), e1 = expf(v.y);
        te[2 * x][n] = e0; te[2 * x + 1][n] = e1;
        __nv_bfloat16 h0 = __float2bfloat16(e0), h1 = __float2bfloat16(e1);
        __nv_bfloat162 hp, lp;
        hp.x = h0; hp.y = h1;
        lp.x = __float2bfloat16(e0 - __bfloat162float(h0));
        lp.y = __float2bfloat16(e1 - __bfloat162float(h1));
        size_t o = ((size_t)b * HW + n0 + n) * HW + m0 + 2 * x;
        *(__nv_bfloat162*)(g_En_h + o) = hp;
        *(__nv_bfloat162*)(g_En_l + o) = lp;
        rsum[i] = e0 + e1;
        cs0 += e0; cs1 += e1;
    }
    sc[y][2 * x] = cs0; sc[y][2 * x + 1] = cs1;
    __syncthreads();
    if (y == 0) {
#pragma unroll
        for (int s = 0; s < 2; ++s) {
            int c = x + s * 32;
            float v = 0.f;
#pragma unroll
            for (int k = 0; k < 8; ++k) v += sc[k][c];
            atomicAdd(&g_colsum[b * HW + m0 + c], v);
        }
    }
#pragma unroll
    for (int m = 16; m; m >>= 1)
#pragma unroll
        for (int i = 0; i < 4; ++i) rsum[i] += __shfl_xor_sync(~0u, rsum[i], m);
    if (x == 0)
#pragma unroll
        for (int i = 0; i < 4; ++i) atomicAdd(&g_rowsum[b * HW + n0 + y + i * 8], rsum[i]);

    int tid = y * 32 + x;
    int mr = tid >> 2, seg = (tid & 3) * 8;
    __nv_bfloat162 hv[4], lv[4];
#pragma unroll
    for (int j = 0; j < 4; ++j) {
        float a = te[mr][seg + 2 * j], c2 = te[mr][seg + 2 * j + 1];
        __nv_bfloat16 ha = __float2bfloat16(a), hc = __float2bfloat16(c2);
        hv[j].x = ha; hv[j].y = hc;
        lv[j].x = __float2bfloat16(a - __bfloat162float(ha));
        lv[j].y = __float2bfloat16(c2 - __bfloat162float(hc));
    }
    size_t o = ((size_t)b * HW + m0 + mr) * HW + n0 + seg;
    *(uint4*)(g_Em_h + o) = *(uint4*)hv;
    *(uint4*)(g_Em_l + o) = *(uint4*)lv;
}

/* ---------------- ew3: normalize + gate + split ---------------- */
__global__ __launch_bounds__(256) void k_ew3(const float* __restrict__ gw, int sel)
{
    __shared__ float sgw[256];
    int tid = threadIdx.x, lane = tid & 31, wid = tid >> 5;
    sgw[tid] = gw[tid];
    __syncthreads();
    const float* af = sel ? g_eattF : g_qattF;
    const float* sums = sel ? g_rowsum : g_colsum;
    __nv_bfloat16* oh = sel ? g_eatt_h : g_qatt_h;
    __nv_bfloat16* ol = sel ? g_eatt_l : g_qatt_l;
    size_t row = (size_t)blockIdx.x * 8 + wid;
    float4 v0 = *(const float4*)(af + row * 256 + lane * 8);
    float4 v1 = *(const float4*)(af + row * 256 + lane * 8 + 4);
    float v[8] = {v0.x, v0.y, v0.z, v0.w, v1.x, v1.y, v1.z, v1.w};
    float dot = 0.f;
#pragma unroll
    for (int j = 0; j < 8; ++j) dot += v[j] * sgw[lane * 8 + j];
#pragma unroll
    for (int m = 16; m; m >>= 1) dot += __shfl_xor_sync(~0u, dot, m);
    float inv = 1.f / sums[row];
    float s = inv / (1.f + expf(-inv * dot));
    __nv_bfloat162 hq[4], lq[4];
#pragma unroll
    for (int j = 0; j < 4; ++j) {
        float a = v[2 * j] * s, c = v[2 * j + 1] * s;
        __nv_bfloat16 ha = __float2bfloat16(a), hc = __float2bfloat16(c);
        hq[j].x = ha; hq[j].y = hc;
        lq[j].x = __float2bfloat16(a - __bfloat162float(ha));
        lq[j].y = __float2bfloat16(c - __bfloat162float(hc));
    }
    *(uint4*)(oh + row * 256 + lane * 8) = *(uint4*)hq;
    *(uint4*)(ol + row * 256 + lane * 8) = *(uint4*)lq;
}

/* ---------------- preps: NO device symbols cross the host ABI ---------------- */
__global__ void k_split_sel(const float* __restrict__ s, int dsel, int n2)
{
    int i = blockIdx.x * 256 + threadIdx.x;
    if (i >= n2) return;
    __nv_bfloat16 *dh, *dl;
    const float* src = s;
    switch (dsel) {
        case 0: dh = g_ex_h; dl = g_ex_l; break;
        case 1: dh = g_q_h;  dl = g_q_l;  break;
        case 2: dh = g_We_h; dl = g_We_l; break;
        case 3: dh = g_W1_h; dl = g_W1_l; break;
        case 4: dh = g_W2_h; dl = g_W2_l; break;
        default: dh = g_ec_h; dl = g_ec_l; src = g_ecF; break;
    }
    float2 v = ((const float2*)src)[i];
    __nv_bfloat16 h0 = __float2bfloat16(v.x), h1 = __float2bfloat16(v.y);
    __nv_bfloat162 hp, lp;
    hp.x = h0; hp.y = h1;
    lp.x = __float2bfloat16(v.x - __bfloat162float(h0));
    lp.y = __float2bfloat16(v.y - __bfloat162float(h1));
    ((__nv_bfloat162*)dh)[i] = hp;
    ((__nv_bfloat162*)dl)[i] = lp;
}

__global__ void k_tsplit(const float* __restrict__ src, int dsel)
{
    __shared__ float t[32][33];
    __nv_bfloat16* dh = dsel ? g_qt_h : g_ext_h;
    __nv_bfloat16* dl = dsel ? g_qt_l : g_ext_l;
    int b = blockIdx.z, c0 = blockIdx.y * 32, n0 = blockIdx.x * 32;
    int tx = threadIdx.x, ty = threadIdx.y;
#pragma unroll
    for (int i = 0; i < 4; ++i)
        t[ty + i * 8][tx] = src[((size_t)b * CCH + c0 + ty + i * 8) * HW + n0 + tx];
    __syncthreads();
#pragma unroll
    for (int i = 0; i < 4; ++i) {
        float v = t[tx][ty + i * 8];
        size_t o = ((size_t)b * HW + n0 + ty + i * 8) * CCH + c0 + tx;
        __nv_bfloat16 h = __float2bfloat16(v);
        dh[o] = h;
        dl[o] = __float2bfloat16(v - __bfloat162float(h));
    }
}

__global__ void k_zero()
{
    int i = blockIdx.x * 256 + threadIdx.x;
    if (i < NB * HW) { g_colsum[i] = 0.f; g_rowsum[i] = 0.f; }
}

/* ---------------- launch ---------------- */
extern "C" void kernel_launch(void* const* d_in, const int* in_sizes, int n_in,
                              void* d_out, int out_size)
{
    const float* in1 = (const float*)d_in[0];
    const float* in2 = (const float*)d_in[1];
    const float* We  = (const float*)d_in[2];
    const float* gw  = (const float*)d_in[3];
    const float* W1  = (const float*)d_in[4];
    const float* W2  = (const float*)d_in[5];
    float* out = (float*)d_out;

    int n2a = (int)(SZ_CN / 2);
    k_split_sel<<<(n2a + 255) / 256, 256>>>(in1, 0, n2a);
    k_split_sel<<<(n2a + 255) / 256, 256>>>(in2, 1, n2a);
    k_split_sel<<<(CCH * CCH / 2 + 255) / 256, 256>>>(We, 2, CCH * CCH / 2);
    k_split_sel<<<(CCH * CCH + 255) / 256, 256>>>(W1, 3, CCH * CCH);
    k_split_sel<<<(CCH * CCH + 255) / 256, 256>>>(W2, 4, CCH * CCH);
    dim3 tgrid(HW / 32, CCH / 32, NB), tblk(32, 8);
    k_tsplit<<<tgrid, tblk>>>(in1, 0);
    k_tsplit<<<tgrid, tblk>>>(in2, 1);
    k_zero<<<(NB * HW + 255) / 256, 256>>>();

    k_g1<<<dim3(CCH / 128, HW / 128, NB), 256, SM_GEMM>>>();
    k_split_sel<<<(n2a + 255) / 256, 256>>>(in1, 5, n2a);  /* g_ecF -> g_ec hi/lo */
    k_g2<<<dim3(HW / 128, HW / 128, NB), 256, SM_GEMM>>>();
    k_ew2<<<dim3(HW / 64, HW / 32, NB), dim3(32, 8)>>>();
    k_att<<<dim3(CCH / 128, HW / 128, NB), 256, SM_GEMM>>>(0);
    k_att<<<dim3(CCH / 128, HW / 128, NB), 256, SM_GEMM>>>(1);
    k_ew3<<<NB * HW / 8, 256>>>(gw, 0);
    k_ew3<<<NB * HW / 8, 256>>>(gw, 1);
    k_conv<<<dim3(HW / 128, CCH / 128, NB), 256, SM_GEMM>>>(out, 0);
    k_conv<<<dim3(HW / 128, CCH / 128, NB), 256, SM_GEMM>>>(out + SZ_CN, 1);
}

// round 8
// speedup vs baseline: 2.8055x; 1.2944x over previous
#include <cuda_runtime.h>
#include <cuda_bf16.h>
#include <mma.h>
#include <cstdint>
#include <math.h>

using namespace nvcuda;

#define NB 4
#define CCH 256
#define HW 4096

#define LDT 40                  /* smem tile row stride, elements */
#define TILEB (128 * LDT * 2)   /* 10240 B */
#define SM_GEMM (4 * TILEB)     /* 40960 B */

typedef wmma::fragment<wmma::matrix_a, 16, 16, 16, __nv_bfloat16, wmma::row_major> FragA;
typedef wmma::fragment<wmma::matrix_b, 16, 16, 16, __nv_bfloat16, wmma::col_major> FragB;
typedef wmma::fragment<wmma::accumulator, 16, 16, 16, float> FragC;

/* ---------------- scratch (no cudaMalloc allowed) ---------------- */
#define SZ_CN ((size_t)NB * CCH * HW)
#define SZ_EE ((size_t)NB * HW * HW)
static __device__ __align__(16) __nv_bfloat16 g_ex_h[SZ_CN], g_ex_l[SZ_CN];   /* in1 [b][c][n] */
static __device__ __align__(16) __nv_bfloat16 g_q_h[SZ_CN],  g_q_l[SZ_CN];    /* in2 [b][c][m] */
static __device__ __align__(16) __nv_bfloat16 g_ext_h[SZ_CN], g_ext_l[SZ_CN]; /* in1^T [b][x][c] */
static __device__ __align__(16) __nv_bfloat16 g_qt_h[SZ_CN],  g_qt_l[SZ_CN];  /* in2^T [b][x][c] */
static __device__ __align__(16) __nv_bfloat16 g_We_h[CCH*CCH], g_We_l[CCH*CCH];
static __device__ __align__(16) __nv_bfloat16 g_W1_h[CCH*2*CCH], g_W1_l[CCH*2*CCH];
static __device__ __align__(16) __nv_bfloat16 g_W2_h[CCH*2*CCH], g_W2_l[CCH*2*CCH];
static __device__ __align__(16) __nv_bfloat16 g_ec_h[SZ_CN], g_ec_l[SZ_CN];   /* [b][n][d] */
static __device__ __align__(16) __nv_bfloat16 g_En_h[SZ_EE], g_En_l[SZ_EE];   /* E [b][n][m] */
static __device__ __align__(16) __nv_bfloat16 g_Em_h[SZ_EE], g_Em_l[SZ_EE];   /* E^T [b][m][n] */
static __device__ __align__(16) __nv_bfloat16 g_qatt_h[SZ_CN], g_qatt_l[SZ_CN]; /* gated [b][m][c] */
static __device__ __align__(16) __nv_bfloat16 g_eatt_h[SZ_CN], g_eatt_l[SZ_CN]; /* gated [b][n][c] */
static __device__ __align__(16) float g_ecF[SZ_CN];
static __device__ __align__(16) float g_qattF[SZ_CN], g_eattF[SZ_CN];
static __device__ float g_colsum[NB*HW], g_rowsum[NB*HW];

__device__ __forceinline__ uint32_t s2u(const void* p) {
    uint32_t a;
    asm("{ .reg .u64 t; cvta.to.shared.u64 t, %1; cvt.u32.u64 %0, t; }" : "=r"(a) : "l"(p));
    return a;
}
__device__ __forceinline__ void cpa16(uint32_t d, const void* g) {
    asm volatile("cp.async.cg.shared.global [%0], [%1], 16;" :: "r"(d), "l"(g));
}

/* ============ wmma 128x128 GEMM core: 3-pass split-bf16, cp.async double buffer ============ */
/* C[r][c] = sum over passes of Apass[r][k] * Bpass[c][k]; A,B tiles k-major in smem.         */
__device__ void gemm_core(char* sm, uint32_t smu,
    const __nv_bfloat16* Ah, const __nv_bfloat16* Al, int lda,
    const __nv_bfloat16* B1h, const __nv_bfloat16* B1l,
    const __nv_bfloat16* B2h, const __nv_bfloat16* B2l, int ksplit, int ldb,
    int K, FragC (&acc)[2][4])
{
    const int t = threadIdx.x, wid = t >> 5;
    const int wm = wid >> 1, wn = wid & 1;  /* 4x2 warps: 32-row x 64-col per warp */
    const int nch = K / 32, total = nch * 3;

#pragma unroll
    for (int mf = 0; mf < 2; ++mf)
#pragma unroll
        for (int nf = 0; nf < 4; ++nf)
            wmma::fill_fragment(acc[mf][nf], 0.0f);

    auto src = [&](int it, const __nv_bfloat16*& A, const __nv_bfloat16*& B) {
        int p = it / nch, k0 = (it - p * nch) * 32;
        A = ((p == 2) ? Al : Ah) + k0;
        const __nv_bfloat16* bh = B1h; const __nv_bfloat16* bl = B1l; int kb = k0;
        if (k0 >= ksplit) { bh = B2h; bl = B2l; kb = k0 - ksplit; }
        B = ((p == 1) ? bl : bh) + kb;
    };
    auto issue = [&](int it) {
        const __nv_bfloat16 *A, *B;
        src(it, A, B);
        uint32_t buf = (uint32_t)(it & 1) * TILEB;
#pragma unroll
        for (int i = 0; i < 2; ++i) {
            int v = t * 2 + i, r = v >> 2, c = v & 3;
            cpa16(smu + buf + r * (LDT * 2) + c * 16, A + (size_t)r * lda + c * 8);
            cpa16(smu + 2 * TILEB + buf + r * (LDT * 2) + c * 16, B + (size_t)r * ldb + c * 8);
        }
        asm volatile("cp.async.commit_group;" ::: "memory");
    };
    auto comp = [&](int buf) {
        const __nv_bfloat16* As = (const __nv_bfloat16*)(sm + buf * TILEB);
        const __nv_bfloat16* Bs = (const __nv_bfloat16*)(sm + 2 * TILEB + buf * TILEB);
#pragma unroll
        for (int kk = 0; kk < 32; kk += 16) {
            FragA af[2]; FragB bfr[4];
#pragma unroll
            for (int mf = 0; mf < 2; ++mf)
                wmma::load_matrix_sync(af[mf], As + (wm * 32 + mf * 16) * LDT + kk, LDT);
#pragma unroll
            for (int nf = 0; nf < 4; ++nf)
                wmma::load_matrix_sync(bfr[nf], Bs + (wn * 64 + nf * 16) * LDT + kk, LDT);
#pragma unroll
            for (int mf = 0; mf < 2; ++mf)
#pragma unroll
                for (int nf = 0; nf < 4; ++nf)
                    wmma::mma_sync(acc[mf][nf], af[mf], bfr[nf], acc[mf][nf]);
        }
    };

    issue(0);
    for (int it = 0; it < total; ++it) {
        if (it + 1 < total) {
            issue(it + 1);
            asm volatile("cp.async.wait_group 1;" ::: "memory");
        } else {
            asm volatile("cp.async.wait_group 0;" ::: "memory");
        }
        __syncthreads();
        comp(it & 1);
        __syncthreads();
    }
}

__device__ __forceinline__ void store_c(FragC (&acc)[2][4], float* C, int ldc)
{
    int wid = threadIdx.x >> 5, wm = wid >> 1, wn = wid & 1;
#pragma unroll
    for (int mf = 0; mf < 2; ++mf)
#pragma unroll
        for (int nf = 0; nf < 4; ++nf)
            wmma::store_matrix_sync(C + (size_t)(wm * 32 + mf * 16) * ldc + wn * 64 + nf * 16,
                                    acc[mf][nf], ldc, wmma::mem_row_major);
}

/* ---------------- GEMM1: ecF[n][d] = ext[n][:] . We[d][:] ---------------- */
__global__ __launch_bounds__(256, 2) void k_g1()
{
    extern __shared__ __align__(128) char sm[];
    uint32_t smu = s2u(sm);
    int b = blockIdx.z, r0 = blockIdx.y * 128, c0 = blockIdx.x * 128;
    FragC acc[2][4];
    size_t ao = ((size_t)b * HW + r0) * CCH;
    gemm_core(sm, smu, g_ext_h + ao, g_ext_l + ao, CCH,
              g_We_h + (size_t)c0 * CCH, g_We_l + (size_t)c0 * CCH,
              g_We_h + (size_t)c0 * CCH, g_We_l + (size_t)c0 * CCH, 1 << 30, CCH, CCH, acc);
    store_c(acc, g_ecF + ao + c0, CCH);
}

/* ---- GEMM2 + fused epilogue: E=__expf(ec.qt^T); En[n][m], Em[m][n] hi/lo; row/col sums ---- */
__global__ __launch_bounds__(256, 2) void k_g2()
{
    extern __shared__ __align__(128) char sm[];
    uint32_t smu = s2u(sm);
    int b = blockIdx.z, r0 = blockIdx.y * 128, c0 = blockIdx.x * 128; /* r=n, c=m */
    int t = threadIdx.x, wid = t >> 5, wm = wid >> 1, wn = wid & 1;
    FragC acc[2][4];
    size_t ao = ((size_t)b * HW + r0) * CCH, bo = ((size_t)b * HW + c0) * CCH;
    gemm_core(sm, smu, g_ec_h + ao, g_ec_l + ao, CCH,
              g_qt_h + bo, g_qt_l + bo, g_qt_h + bo, g_qt_l + bo, 1 << 30, CCH, CCH, acc);

#pragma unroll
    for (int mf = 0; mf < 2; ++mf)
#pragma unroll
        for (int nf = 0; nf < 4; ++nf)
#pragma unroll
            for (int i = 0; i < acc[mf][nf].num_elements; ++i)
                acc[mf][nf].x[i] = __expf(acc[mf][nf].x[i]);

    /* stage halves of the exp'd tile through smem (reuses gemm buffers, 64x132 fp32) */
    float* stg = (float*)sm;
    const int LDS2 = 132;
    for (int h = 0; h < 2; ++h) {
        __syncthreads();
        if ((wm >> 1) == h) {
            int lm = wm & 1;
#pragma unroll
            for (int mf = 0; mf < 2; ++mf)
#pragma unroll
                for (int nf = 0; nf < 4; ++nf)
                    wmma::store_matrix_sync(stg + (lm * 32 + mf * 16) * LDS2 + wn * 64 + nf * 16,
                                            acc[mf][nf], LDS2, wmma::mem_row_major);
        }
        __syncthreads();
        /* En rows: thread -> (row=t>>2, 32-col segment seg=t&3) */
        {
            int row = t >> 2, seg = t & 3;
            const float* sp = stg + row * LDS2 + seg * 32;
            size_t o = ((size_t)b * HW + r0 + h * 64 + row) * HW + c0 + seg * 32;
            float rs = 0.f;
#pragma unroll
            for (int q = 0; q < 4; ++q) {
                __nv_bfloat162 hv[4], lv[4];
#pragma unroll
                for (int j = 0; j < 4; ++j) {
                    float a = sp[q * 8 + 2 * j], c2 = sp[q * 8 + 2 * j + 1];
                    rs += a + c2;
                    __nv_bfloat16 ha = __float2bfloat16(a), hc = __float2bfloat16(c2);
                    hv[j].x = ha; hv[j].y = hc;
                    lv[j].x = __float2bfloat16(a - __bfloat162float(ha));
                    lv[j].y = __float2bfloat16(c2 - __bfloat162float(hc));
                }
                *(uint4*)(g_En_h + o + q * 8) = *(uint4*)hv;
                *(uint4*)(g_En_l + o + q * 8) = *(uint4*)lv;
            }
            rs += __shfl_xor_sync(~0u, rs, 1);
            rs += __shfl_xor_sync(~0u, rs, 2);
            if (seg == 0) atomicAdd(&g_rowsum[b * HW + r0 + h * 64 + row], rs);
        }
        /* Em cols: thread -> (col=t>>1, 32-row segment rh=t&1) */
        {
            int col = t >> 1, rh = t & 1;
            const float* sp = stg + (rh * 32) * LDS2 + col;
            size_t o = ((size_t)b * HW + c0 + col) * HW + r0 + h * 64 + rh * 32;
            float cs = 0.f;
#pragma unroll
            for (int q = 0; q < 4; ++q) {
                __nv_bfloat162 hv[4], lv[4];
#pragma unroll
                for (int j = 0; j < 4; ++j) {
                    float a = sp[(q * 8 + 2 * j) * LDS2], c2 = sp[(q * 8 + 2 * j + 1) * LDS2];
                    cs += a + c2;
                    __nv_bfloat16 ha = __float2bfloat16(a), hc = __float2bfloat16(c2);
                    hv[j].x = ha; hv[j].y = hc;
                    lv[j].x = __float2bfloat16(a - __bfloat162float(ha));
                    lv[j].y = __float2bfloat16(c2 - __bfloat162float(hc));
                }
                *(uint4*)(g_Em_h + o + q * 8) = *(uint4*)hv;
                *(uint4*)(g_Em_l + o + q * 8) = *(uint4*)lv;
            }
            cs += __shfl_xor_sync(~0u, cs, 1);
            if (rh == 0) atomicAdd(&g_colsum[b * HW + c0 + col], cs);
        }
    }
}

/* ---------------- GEMM3/4: attF[x][c] = E_x[:] . inp[c][:] (raw) ---------------- */
__global__ __launch_bounds__(256, 2) void k_att(int sel)
{
    extern __shared__ __align__(128) char sm[];
    uint32_t smu = s2u(sm);
    int b = blockIdx.z, r0 = blockIdx.y * 128, c0 = blockIdx.x * 128;
    const __nv_bfloat16 *Ah, *Al, *Bh, *Bl; float* Cf;
    if (sel == 0) { Ah = g_Em_h; Al = g_Em_l; Bh = g_ex_h; Bl = g_ex_l; Cf = g_qattF; }
    else          { Ah = g_En_h; Al = g_En_l; Bh = g_q_h;  Bl = g_q_l;  Cf = g_eattF; }
    FragC acc[2][4];
    size_t ao = ((size_t)b * HW + r0) * HW, bo = ((size_t)b * CCH + c0) * HW;
    gemm_core(sm, smu, Ah + ao, Al + ao, HW, Bh + bo, Bl + bo, Bh + bo, Bl + bo, 1 << 30, HW, HW, acc);
    store_c(acc, Cf + ((size_t)b * HW + r0) * CCH + c0, CCH);
}

/* ---------------- conv: out[o][x] = W[o][0:512] . [att | inp_t][x][0:512] ---------------- */
__global__ __launch_bounds__(256, 2) void k_conv(float* __restrict__ out, int w)
{
    extern __shared__ __align__(128) char sm[];
    uint32_t smu = s2u(sm);
    int b = blockIdx.z, o0 = blockIdx.y * 128, x0 = blockIdx.x * 128;
    const __nv_bfloat16 *Wh, *Wl, *B1h, *B1l, *B2h, *B2l;
    if (w == 0) { Wh = g_W1_h; Wl = g_W1_l; B1h = g_eatt_h; B1l = g_eatt_l; B2h = g_ext_h; B2l = g_ext_l; }
    else        { Wh = g_W2_h; Wl = g_W2_l; B1h = g_qatt_h; B1l = g_qatt_l; B2h = g_qt_h;  B2l = g_qt_l; }
    FragC acc[2][4];
    size_t bo = ((size_t)b * HW + x0) * CCH;
    gemm_core(sm, smu, Wh + (size_t)o0 * 512, Wl + (size_t)o0 * 512, 512,
              B1h + bo, B1l + bo, B2h + bo, B2l + bo, 256, CCH, 512, acc);
    store_c(acc, out + ((size_t)b * CCH + o0) * HW + x0, HW);
}

/* ---------------- ew3: normalize + gate + split ---------------- */
__global__ __launch_bounds__(256) void k_ew3(const float* __restrict__ gw, int sel)
{
    __shared__ float sgw[256];
    int tid = threadIdx.x, lane = tid & 31, wid = tid >> 5;
    sgw[tid] = gw[tid];
    __syncthreads();
    const float* af = sel ? g_eattF : g_qattF;
    const float* sums = sel ? g_rowsum : g_colsum;
    __nv_bfloat16* oh = sel ? g_eatt_h : g_qatt_h;
    __nv_bfloat16* ol = sel ? g_eatt_l : g_qatt_l;
    size_t row = (size_t)blockIdx.x * 8 + wid;
    float4 v0 = *(const float4*)(af + row * 256 + lane * 8);
    float4 v1 = *(const float4*)(af + row * 256 + lane * 8 + 4);
    float v[8] = {v0.x, v0.y, v0.z, v0.w, v1.x, v1.y, v1.z, v1.w};
    float dot = 0.f;
#pragma unroll
    for (int j = 0; j < 8; ++j) dot += v[j] * sgw[lane * 8 + j];
#pragma unroll
    for (int m = 16; m; m >>= 1) dot += __shfl_xor_sync(~0u, dot, m);
    float inv = 1.f / sums[row];
    float s = inv / (1.f + expf(-inv * dot));
    __nv_bfloat162 hq[4], lq[4];
#pragma unroll
    for (int j = 0; j < 4; ++j) {
        float a = v[2 * j] * s, c = v[2 * j + 1] * s;
        __nv_bfloat16 ha = __float2bfloat16(a), hc = __float2bfloat16(c);
        hq[j].x = ha; hq[j].y = hc;
        lq[j].x = __float2bfloat16(a - __bfloat162float(ha));
        lq[j].y = __float2bfloat16(c - __bfloat162float(hc));
    }
    *(uint4*)(oh + row * 256 + lane * 8) = *(uint4*)hq;
    *(uint4*)(ol + row * 256 + lane * 8) = *(uint4*)lq;
}

/* ---------------- preps: NO device symbols cross the host ABI ---------------- */
__global__ void k_split_sel(const float* __restrict__ s, int dsel, int n2)
{
    int i = blockIdx.x * 256 + threadIdx.x;
    if (i >= n2) return;
    __nv_bfloat16 *dh, *dl;
    const float* src = s;
    switch (dsel) {
        case 0: dh = g_ex_h; dl = g_ex_l; break;
        case 1: dh = g_q_h;  dl = g_q_l;  break;
        case 2: dh = g_We_h; dl = g_We_l; break;
        case 3: dh = g_W1_h; dl = g_W1_l; break;
        case 4: dh = g_W2_h; dl = g_W2_l; break;
        default: dh = g_ec_h; dl = g_ec_l; src = g_ecF; break;
    }
    float2 v = ((const float2*)src)[i];
    __nv_bfloat16 h0 = __float2bfloat16(v.x), h1 = __float2bfloat16(v.y);
    __nv_bfloat162 hp, lp;
    hp.x = h0; hp.y = h1;
    lp.x = __float2bfloat16(v.x - __bfloat162float(h0));
    lp.y = __float2bfloat16(v.y - __bfloat162float(h1));
    ((__nv_bfloat162*)dh)[i] = hp;
    ((__nv_bfloat162*)dl)[i] = lp;
}

__global__ void k_tsplit(const float* __restrict__ src, int dsel)
{
    __shared__ float t[32][33];
    __nv_bfloat16* dh = dsel ? g_qt_h : g_ext_h;
    __nv_bfloat16* dl = dsel ? g_qt_l : g_ext_l;
    int b = blockIdx.z, c0 = blockIdx.y * 32, n0 = blockIdx.x * 32;
    int tx = threadIdx.x, ty = threadIdx.y;
#pragma unroll
    for (int i = 0; i < 4; ++i)
        t[ty + i * 8][tx] = src[((size_t)b * CCH + c0 + ty + i * 8) * HW + n0 + tx];
    __syncthreads();
#pragma unroll
    for (int i = 0; i < 4; ++i) {
        float v = t[tx][ty + i * 8];
        size_t o = ((size_t)b * HW + n0 + ty + i * 8) * CCH + c0 + tx;
        __nv_bfloat16 h = __float2bfloat16(v);
        dh[o] = h;
        dl[o] = __float2bfloat16(v - __bfloat162float(h));
    }
}

__global__ void k_zero()
{
    int i = blockIdx.x * 256 + threadIdx.x;
    if (i < NB * HW) { g_colsum[i] = 0.f; g_rowsum[i] = 0.f; }
}

/* ---------------- launch ---------------- */
extern "C" void kernel_launch(void* const* d_in, const int* in_sizes, int n_in,
                              void* d_out, int out_size)
{
    const float* in1 = (const float*)d_in[0];
    const float* in2 = (const float*)d_in[1];
    const float* We  = (const float*)d_in[2];
    const float* gw  = (const float*)d_in[3];
    const float* W1  = (const float*)d_in[4];
    const float* W2  = (const float*)d_in[5];
    float* out = (float*)d_out;

    int n2a = (int)(SZ_CN / 2);
    k_split_sel<<<(n2a + 255) / 256, 256>>>(in1, 0, n2a);
    k_split_sel<<<(n2a + 255) / 256, 256>>>(in2, 1, n2a);
    k_split_sel<<<(CCH * CCH / 2 + 255) / 256, 256>>>(We, 2, CCH * CCH / 2);
    k_split_sel<<<(CCH * CCH + 255) / 256, 256>>>(W1, 3, CCH * CCH);
    k_split_sel<<<(CCH * CCH + 255) / 256, 256>>>(W2, 4, CCH * CCH);
    dim3 tgrid(HW / 32, CCH / 32, NB), tblk(32, 8);
    k_tsplit<<<tgrid, tblk>>>(in1, 0);
    k_tsplit<<<tgrid, tblk>>>(in2, 1);
    k_zero<<<(NB * HW + 255) / 256, 256>>>();

    k_g1<<<dim3(CCH / 128, HW / 128, NB), 256, SM_GEMM>>>();
    k_split_sel<<<(n2a + 255) / 256, 256>>>(in1, 5, n2a);  /* g_ecF -> g_ec hi/lo */
    k_g2<<<dim3(HW / 128, HW / 128, NB), 256, SM_GEMM>>>();
    k_att<<<dim3(CCH / 128, HW / 128, NB), 256, SM_GEMM>>>(0);
    k_att<<<dim3(CCH / 128, HW / 128, NB), 256, SM_GEMM>>>(1);
    k_ew3<<<NB * HW / 8, 256>>>(gw, 0);
    k_ew3<<<NB * HW / 8, 256>>>(gw, 1);
    k_conv<<<dim3(HW / 128, CCH / 128, NB), 256, SM_GEMM>>>(out, 0);
    k_conv<<<dim3(HW / 128, CCH / 128, NB), 256, SM_GEMM>>>(out + SZ_CN, 1);
}

// round 9
// speedup vs baseline: 2.8180x; 1.0044x over previous
#include <cuda_runtime.h>
#include <cuda_bf16.h>
#include <mma.h>
#include <cstdint>
#include <math.h>

using namespace nvcuda;

#define NB 4
#define CCH 256
#define HW 4096

#define LDT 40                  /* smem tile row stride, elements */
#define TILEB (128 * LDT * 2)   /* 10240 B per operand tile */
#define STGB (2 * TILEB)        /* A+B per stage = 20480 B */
#define NSTG 3
#define SM_GEMM (NSTG * STGB)   /* 61440 B */

typedef wmma::fragment<wmma::matrix_a, 16, 16, 16, __nv_bfloat16, wmma::row_major> FragA;
typedef wmma::fragment<wmma::matrix_b, 16, 16, 16, __nv_bfloat16, wmma::col_major> FragB;
typedef wmma::fragment<wmma::accumulator, 16, 16, 16, float> FragC;

/* ---------------- scratch (no cudaMalloc allowed) ---------------- */
#define SZ_CN ((size_t)NB * CCH * HW)
#define SZ_EE ((size_t)NB * HW * HW)
static __device__ __align__(16) __nv_bfloat16 g_ex_h[SZ_CN], g_ex_l[SZ_CN];   /* in1 [b][c][n] */
static __device__ __align__(16) __nv_bfloat16 g_q_h[SZ_CN],  g_q_l[SZ_CN];    /* in2 [b][c][m] */
static __device__ __align__(16) __nv_bfloat16 g_ext_h[SZ_CN], g_ext_l[SZ_CN]; /* in1^T [b][x][c] */
static __device__ __align__(16) __nv_bfloat16 g_qt_h[SZ_CN],  g_qt_l[SZ_CN];  /* in2^T [b][x][c] */
static __device__ __align__(16) __nv_bfloat16 g_We_h[CCH*CCH], g_We_l[CCH*CCH];
static __device__ __align__(16) __nv_bfloat16 g_W1_h[CCH*2*CCH], g_W1_l[CCH*2*CCH];
static __device__ __align__(16) __nv_bfloat16 g_W2_h[CCH*2*CCH], g_W2_l[CCH*2*CCH];
static __device__ __align__(16) __nv_bfloat16 g_ec_h[SZ_CN], g_ec_l[SZ_CN];   /* [b][n][d] */
static __device__ __align__(16) __nv_bfloat16 g_En_h[SZ_EE], g_En_l[SZ_EE];   /* E [b][n][m] */
static __device__ __align__(16) __nv_bfloat16 g_Em_h[SZ_EE], g_Em_l[SZ_EE];   /* E^T [b][m][n] */
static __device__ __align__(16) __nv_bfloat16 g_qatt_h[SZ_CN], g_qatt_l[SZ_CN]; /* gated [b][m][c] */
static __device__ __align__(16) __nv_bfloat16 g_eatt_h[SZ_CN], g_eatt_l[SZ_CN]; /* gated [b][n][c] */
static __device__ __align__(16) float g_ecF[SZ_CN];
static __device__ __align__(16) float g_qattF[SZ_CN], g_eattF[SZ_CN];
static __device__ float g_colsum[NB*HW], g_rowsum[NB*HW];

__device__ __forceinline__ uint32_t s2u(const void* p) {
    uint32_t a;
    asm("{ .reg .u64 t; cvta.to.shared.u64 t, %1; cvt.u32.u64 %0, t; }" : "=r"(a) : "l"(p));
    return a;
}
__device__ __forceinline__ void cpa16(uint32_t d, const void* g) {
    asm volatile("cp.async.cg.shared.global [%0], [%1], 16;" :: "r"(d), "l"(g));
}

/* ============ wmma 128x128 GEMM core: 3-pass split-bf16, 3-stage cp.async ============ */
/* C[r][c] = sum over passes of Apass[r][k] * Bpass[c][k]; A,B tiles k-major in smem.    */
__device__ void gemm_core(char* sm, uint32_t smu,
    const __nv_bfloat16* Ah, const __nv_bfloat16* Al, int lda,
    const __nv_bfloat16* B1h, const __nv_bfloat16* B1l,
    const __nv_bfloat16* B2h, const __nv_bfloat16* B2l, int ksplit, int ldb,
    int K, FragC (&acc)[2][4])
{
    const int t = threadIdx.x, wid = t >> 5;
    const int wm = wid >> 1, wn = wid & 1;  /* 4x2 warps: 32-row x 64-col per warp */
    const int nch = K / 32, total = nch * 3;

#pragma unroll
    for (int mf = 0; mf < 2; ++mf)
#pragma unroll
        for (int nf = 0; nf < 4; ++nf)
            wmma::fill_fragment(acc[mf][nf], 0.0f);

    auto src = [&](int it, const __nv_bfloat16*& A, const __nv_bfloat16*& B) {
        int p = it / nch, k0 = (it - p * nch) * 32;
        A = ((p == 2) ? Al : Ah) + k0;
        const __nv_bfloat16* bh = B1h; const __nv_bfloat16* bl = B1l; int kb = k0;
        if (k0 >= ksplit) { bh = B2h; bl = B2l; kb = k0 - ksplit; }
        B = ((p == 1) ? bl : bh) + kb;
    };
    auto issue = [&](int it) {
        const __nv_bfloat16 *A, *B;
        src(it, A, B);
        uint32_t buf = (uint32_t)(it % NSTG) * STGB;
#pragma unroll
        for (int i = 0; i < 2; ++i) {
            int v = t * 2 + i, r = v >> 2, c = v & 3;
            cpa16(smu + buf + r * (LDT * 2) + c * 16, A + (size_t)r * lda + c * 8);
            cpa16(smu + buf + TILEB + r * (LDT * 2) + c * 16, B + (size_t)r * ldb + c * 8);
        }
        asm volatile("cp.async.commit_group;" ::: "memory");
    };
    auto comp = [&](int stg) {
        const __nv_bfloat16* As = (const __nv_bfloat16*)(sm + stg * STGB);
        const __nv_bfloat16* Bs = (const __nv_bfloat16*)(sm + stg * STGB + TILEB);
#pragma unroll
        for (int kk = 0; kk < 32; kk += 16) {
            FragA af[2]; FragB bfr[4];
#pragma unroll
            for (int mf = 0; mf < 2; ++mf)
                wmma::load_matrix_sync(af[mf], As + (wm * 32 + mf * 16) * LDT + kk, LDT);
#pragma unroll
            for (int nf = 0; nf < 4; ++nf)
                wmma::load_matrix_sync(bfr[nf], Bs + (wn * 64 + nf * 16) * LDT + kk, LDT);
#pragma unroll
            for (int mf = 0; mf < 2; ++mf)
#pragma unroll
                for (int nf = 0; nf < 4; ++nf)
                    wmma::mma_sync(acc[mf][nf], af[mf], bfr[nf], acc[mf][nf]);
        }
    };

    issue(0);
    if (total > 1) issue(1);
    for (int it = 0; it < total; ++it) {
        if (it + 1 < total)
            asm volatile("cp.async.wait_group 1;" ::: "memory");
        else
            asm volatile("cp.async.wait_group 0;" ::: "memory");
        __syncthreads();                 /* stage `it` visible; comp(it-1) done by all */
        if (it + 2 < total) issue(it + 2);
        comp(it % NSTG);
    }
}

__device__ __forceinline__ void store_c(FragC (&acc)[2][4], float* C, int ldc)
{
    int wid = threadIdx.x >> 5, wm = wid >> 1, wn = wid & 1;
#pragma unroll
    for (int mf = 0; mf < 2; ++mf)
#pragma unroll
        for (int nf = 0; nf < 4; ++nf)
            wmma::store_matrix_sync(C + (size_t)(wm * 32 + mf * 16) * ldc + wn * 64 + nf * 16,
                                    acc[mf][nf], ldc, wmma::mem_row_major);
}

/* ---------------- GEMM1: ecF[n][d] = ext[n][:] . We[d][:] ---------------- */
__global__ __launch_bounds__(256, 2) void k_g1()
{
    extern __shared__ __align__(128) char sm[];
    uint32_t smu = s2u(sm);
    int b = blockIdx.z, r0 = blockIdx.y * 128, c0 = blockIdx.x * 128;
    FragC acc[2][4];
    size_t ao = ((size_t)b * HW + r0) * CCH;
    gemm_core(sm, smu, g_ext_h + ao, g_ext_l + ao, CCH,
              g_We_h + (size_t)c0 * CCH, g_We_l + (size_t)c0 * CCH,
              g_We_h + (size_t)c0 * CCH, g_We_l + (size_t)c0 * CCH, 1 << 30, CCH, CCH, acc);
    __syncthreads();
    store_c(acc, g_ecF + ao + c0, CCH);
}

/* ---- GEMM2 + fused epilogue: E=__expf(ec.qt^T); En[n][m], Em[m][n] hi/lo; row/col sums ---- */
__global__ __launch_bounds__(256, 2) void k_g2()
{
    extern __shared__ __align__(128) char sm[];
    uint32_t smu = s2u(sm);
    int b = blockIdx.z, r0 = blockIdx.y * 128, c0 = blockIdx.x * 128; /* r=n, c=m */
    int t = threadIdx.x, wid = t >> 5, wm = wid >> 1, wn = wid & 1;
    FragC acc[2][4];
    size_t ao = ((size_t)b * HW + r0) * CCH, bo = ((size_t)b * HW + c0) * CCH;
    gemm_core(sm, smu, g_ec_h + ao, g_ec_l + ao, CCH,
              g_qt_h + bo, g_qt_l + bo, g_qt_h + bo, g_qt_l + bo, 1 << 30, CCH, CCH, acc);

#pragma unroll
    for (int mf = 0; mf < 2; ++mf)
#pragma unroll
        for (int nf = 0; nf < 4; ++nf)
#pragma unroll
            for (int i = 0; i < acc[mf][nf].num_elements; ++i)
                acc[mf][nf].x[i] = __expf(acc[mf][nf].x[i]);

    /* stage halves of the exp'd tile through smem (reuses gemm buffers, 64x132 fp32) */
    float* stg = (float*)sm;
    const int LDS2 = 132;
    for (int h = 0; h < 2; ++h) {
        __syncthreads();
        if ((wm >> 1) == h) {
            int lm = wm & 1;
#pragma unroll
            for (int mf = 0; mf < 2; ++mf)
#pragma unroll
                for (int nf = 0; nf < 4; ++nf)
                    wmma::store_matrix_sync(stg + (lm * 32 + mf * 16) * LDS2 + wn * 64 + nf * 16,
                                            acc[mf][nf], LDS2, wmma::mem_row_major);
        }
        __syncthreads();
        /* En rows: thread -> (row=t>>2, 32-col segment seg=t&3) */
        {
            int row = t >> 2, seg = t & 3;
            const float* sp = stg + row * LDS2 + seg * 32;
            size_t o = ((size_t)b * HW + r0 + h * 64 + row) * HW + c0 + seg * 32;
            float rs = 0.f;
#pragma unroll
            for (int q = 0; q < 4; ++q) {
                __nv_bfloat162 hv[4], lv[4];
#pragma unroll
                for (int j = 0; j < 4; ++j) {
                    float a = sp[q * 8 + 2 * j], c2 = sp[q * 8 + 2 * j + 1];
                    rs += a + c2;
                    __nv_bfloat16 ha = __float2bfloat16(a), hc = __float2bfloat16(c2);
                    hv[j].x = ha; hv[j].y = hc;
                    lv[j].x = __float2bfloat16(a - __bfloat162float(ha));
                    lv[j].y = __float2bfloat16(c2 - __bfloat162float(hc));
                }
                *(uint4*)(g_En_h + o + q * 8) = *(uint4*)hv;
                *(uint4*)(g_En_l + o + q * 8) = *(uint4*)lv;
            }
            rs += __shfl_xor_sync(~0u, rs, 1);
            rs += __shfl_xor_sync(~0u, rs, 2);
            if (seg == 0) atomicAdd(&g_rowsum[b * HW + r0 + h * 64 + row], rs);
        }
        /* Em cols: thread -> (col=t>>1, 32-row segment rh=t&1) */
        {
            int col = t >> 1, rh = t & 1;
            const float* sp = stg + (rh * 32) * LDS2 + col;
            size_t o = ((size_t)b * HW + c0 + col) * HW + r0 + h * 64 + rh * 32;
            float cs = 0.f;
#pragma unroll
            for (int q = 0; q < 4; ++q) {
                __nv_bfloat162 hv[4], lv[4];
#pragma unroll
                for (int j = 0; j < 4; ++j) {
                    float a = sp[(q * 8 + 2 * j) * LDS2], c2 = sp[(q * 8 + 2 * j + 1) * LDS2];
                    cs += a + c2;
                    __nv_bfloat16 ha = __float2bfloat16(a), hc = __float2bfloat16(c2);
                    hv[j].x = ha; hv[j].y = hc;
                    lv[j].x = __float2bfloat16(a - __bfloat162float(ha));
                    lv[j].y = __float2bfloat16(c2 - __bfloat162float(hc));
                }
                *(uint4*)(g_Em_h + o + q * 8) = *(uint4*)hv;
                *(uint4*)(g_Em_l + o + q * 8) = *(uint4*)lv;
            }
            cs += __shfl_xor_sync(~0u, cs, 1);
            if (rh == 0) atomicAdd(&g_colsum[b * HW + c0 + col], cs);
        }
    }
}

/* ------ GEMM3/4 merged: attF[x][c] = E_x[:] . inp[c][:] (raw); z -> (b, sel) ------ */
__global__ __launch_bounds__(256, 2) void k_att()
{
    extern __shared__ __align__(128) char sm[];
    uint32_t smu = s2u(sm);
    int z = blockIdx.z, b = z >> 1, sel = z & 1;
    int r0 = blockIdx.y * 128, c0 = blockIdx.x * 128;
    const __nv_bfloat16 *Ah, *Al, *Bh, *Bl; float* Cf;
    if (sel == 0) { Ah = g_Em_h; Al = g_Em_l; Bh = g_ex_h; Bl = g_ex_l; Cf = g_qattF; }
    else          { Ah = g_En_h; Al = g_En_l; Bh = g_q_h;  Bl = g_q_l;  Cf = g_eattF; }
    FragC acc[2][4];
    size_t ao = ((size_t)b * HW + r0) * HW, bo = ((size_t)b * CCH + c0) * HW;
    gemm_core(sm, smu, Ah + ao, Al + ao, HW, Bh + bo, Bl + bo, Bh + bo, Bl + bo, 1 << 30, HW, HW, acc);
    __syncthreads();
    store_c(acc, Cf + ((size_t)b * HW + r0) * CCH + c0, CCH);
}

/* ------ conv merged: out[o][x] = W[o][0:512].[att|inp_t][x][0:512]; z -> (b, w) ------ */
__global__ __launch_bounds__(256, 2) void k_conv(float* __restrict__ out)
{
    extern __shared__ __align__(128) char sm[];
    uint32_t smu = s2u(sm);
    int z = blockIdx.z, b = z >> 1, w = z & 1;
    int o0 = blockIdx.y * 128, x0 = blockIdx.x * 128;
    const __nv_bfloat16 *Wh, *Wl, *B1h, *B1l, *B2h, *B2l;
    if (w == 0) { Wh = g_W1_h; Wl = g_W1_l; B1h = g_eatt_h; B1l = g_eatt_l; B2h = g_ext_h; B2l = g_ext_l; }
    else        { Wh = g_W2_h; Wl = g_W2_l; B1h = g_qatt_h; B1l = g_qatt_l; B2h = g_qt_h;  B2l = g_qt_l; }
    FragC acc[2][4];
    size_t bo = ((size_t)b * HW + x0) * CCH;
    gemm_core(sm, smu, Wh + (size_t)o0 * 512, Wl + (size_t)o0 * 512, 512,
              B1h + bo, B1l + bo, B2h + bo, B2l + bo, 256, CCH, 512, acc);
    __syncthreads();
    store_c(acc, out + (size_t)w * SZ_CN + ((size_t)b * CCH + o0) * HW + x0, HW);
}

/* ---------------- ew3 merged: normalize + gate + split; y -> sel ---------------- */
__global__ __launch_bounds__(256) void k_ew3(const float* __restrict__ gw)
{
    __shared__ float sgw[256];
    int tid = threadIdx.x, lane = tid & 31, wid = tid >> 5;
    int sel = blockIdx.y;
    sgw[tid] = gw[tid];
    __syncthreads();
    const float* af = sel ? g_eattF : g_qattF;
    const float* sums = sel ? g_rowsum : g_colsum;
    __nv_bfloat16* oh = sel ? g_eatt_h : g_qatt_h;
    __nv_bfloat16* ol = sel ? g_eatt_l : g_qatt_l;
    size_t row = (size_t)blockIdx.x * 8 + wid;
    float4 v0 = *(const float4*)(af + row * 256 + lane * 8);
    float4 v1 = *(const float4*)(af + row * 256 + lane * 8 + 4);
    float v[8] = {v0.x, v0.y, v0.z, v0.w, v1.x, v1.y, v1.z, v1.w};
    float dot = 0.f;
#pragma unroll
    for (int j = 0; j < 8; ++j) dot += v[j] * sgw[lane * 8 + j];
#pragma unroll
    for (int m = 16; m; m >>= 1) dot += __shfl_xor_sync(~0u, dot, m);
    float inv = 1.f / sums[row];
    float s = inv / (1.f + expf(-inv * dot));
    __nv_bfloat162 hq[4], lq[4];
#pragma unroll
    for (int j = 0; j < 4; ++j) {
        float a = v[2 * j] * s, c = v[2 * j + 1] * s;
        __nv_bfloat16 ha = __float2bfloat16(a), hc = __float2bfloat16(c);
        hq[j].x = ha; hq[j].y = hc;
        lq[j].x = __float2bfloat16(a - __bfloat162float(ha));
        lq[j].y = __float2bfloat16(c - __bfloat162float(hc));
    }
    *(uint4*)(oh + row * 256 + lane * 8) = *(uint4*)hq;
    *(uint4*)(ol + row * 256 + lane * 8) = *(uint4*)lq;
}

/* ---------------- preps: NO device symbols cross the host ABI ---------------- */
__global__ void k_split_sel(const float* __restrict__ s, int dsel, int n2)
{
    int i = blockIdx.x * 256 + threadIdx.x;
    if (i >= n2) return;
    __nv_bfloat16 *dh, *dl;
    const float* src = s;
    switch (dsel) {
        case 0: dh = g_ex_h; dl = g_ex_l; break;
        case 1: dh = g_q_h;  dl = g_q_l;  break;
        case 2: dh = g_We_h; dl = g_We_l; break;
        case 3: dh = g_W1_h; dl = g_W1_l; break;
        case 4: dh = g_W2_h; dl = g_W2_l; break;
        default: dh = g_ec_h; dl = g_ec_l; src = g_ecF; break;
    }
    float2 v = ((const float2*)src)[i];
    __nv_bfloat16 h0 = __float2bfloat16(v.x), h1 = __float2bfloat16(v.y);
    __nv_bfloat162 hp, lp;
    hp.x = h0; hp.y = h1;
    lp.x = __float2bfloat16(v.x - __bfloat162float(h0));
    lp.y = __float2bfloat16(v.y - __bfloat162float(h1));
    ((__nv_bfloat162*)dh)[i] = hp;
    ((__nv_bfloat162*)dl)[i] = lp;
}

__global__ void k_tsplit(const float* __restrict__ src, int dsel)
{
    __shared__ float t[32][33];
    __nv_bfloat16* dh = dsel ? g_qt_h : g_ext_h;
    __nv_bfloat16* dl = dsel ? g_qt_l : g_ext_l;
    int b = blockIdx.z, c0 = blockIdx.y * 32, n0 = blockIdx.x * 32;
    int tx = threadIdx.x, ty = threadIdx.y;
#pragma unroll
    for (int i = 0; i < 4; ++i)
        t[ty + i * 8][tx] = src[((size_t)b * CCH + c0 + ty + i * 8) * HW + n0 + tx];
    __syncthreads();
#pragma unroll
    for (int i = 0; i < 4; ++i) {
        float v = t[tx][ty + i * 8];
        size_t o = ((size_t)b * HW + n0 + ty + i * 8) * CCH + c0 + tx;
        __nv_bfloat16 h = __float2bfloat16(v);
        dh[o] = h;
        dl[o] = __float2bfloat16(v - __bfloat162float(h));
    }
}

__global__ void k_zero()
{
    int i = blockIdx.x * 256 + threadIdx.x;
    if (i < NB * HW) { g_colsum[i] = 0.f; g_rowsum[i] = 0.f; }
}

/* ---------------- launch ---------------- */
extern "C" void kernel_launch(void* const* d_in, const int* in_sizes, int n_in,
                              void* d_out, int out_size)
{
    const float* in1 = (const float*)d_in[0];
    const float* in2 = (const float*)d_in[1];
    const float* We  = (const float*)d_in[2];
    const float* gw  = (const float*)d_in[3];
    const float* W1  = (const float*)d_in[4];
    const float* W2  = (const float*)d_in[5];
    float* out = (float*)d_out;

    cudaFuncSetAttribute(k_g1,   cudaFuncAttributeMaxDynamicSharedMemorySize, SM_GEMM);
    cudaFuncSetAttribute(k_g2,   cudaFuncAttributeMaxDynamicSharedMemorySize, SM_GEMM);
    cudaFuncSetAttribute(k_att,  cudaFuncAttributeMaxDynamicSharedMemorySize, SM_GEMM);
    cudaFuncSetAttribute(k_conv, cudaFuncAttributeMaxDynamicSharedMemorySize, SM_GEMM);

    int n2a = (int)(SZ_CN / 2);
    k_split_sel<<<(n2a + 255) / 256, 256>>>(in1, 0, n2a);
    k_split_sel<<<(n2a + 255) / 256, 256>>>(in2, 1, n2a);
    k_split_sel<<<(CCH * CCH / 2 + 255) / 256, 256>>>(We, 2, CCH * CCH / 2);
    k_split_sel<<<(CCH * CCH + 255) / 256, 256>>>(W1, 3, CCH * CCH);
    k_split_sel<<<(CCH * CCH + 255) / 256, 256>>>(W2, 4, CCH * CCH);
    dim3 tgrid(HW / 32, CCH / 32, NB), tblk(32, 8);
    k_tsplit<<<tgrid, tblk>>>(in1, 0);
    k_tsplit<<<tgrid, tblk>>>(in2, 1);
    k_zero<<<(NB * HW + 255) / 256, 256>>>();

    k_g1<<<dim3(CCH / 128, HW / 128, NB), 256, SM_GEMM>>>();
    k_split_sel<<<(n2a + 255) / 256, 256>>>(in1, 5, n2a);  /* g_ecF -> g_ec hi/lo */
    k_g2<<<dim3(HW / 128, HW / 128, NB), 256, SM_GEMM>>>();
    k_att<<<dim3(CCH / 128, HW / 128, NB * 2), 256, SM_GEMM>>>();
    k_ew3<<<dim3(NB * HW / 8, 2), 256>>>(gw);
    k_conv<<<dim3(HW / 128, CCH / 128, NB * 2), 256, SM_GEMM>>>(out);
}

// round 12
// speedup vs baseline: 2.8446x; 1.0094x over previous
#include <cuda_runtime.h>
#include <cuda_bf16.h>
#include <mma.h>
#include <cstdint>
#include <math.h>

using namespace nvcuda;

#define NB 4
#define CCH 256
#define HW 4096

#define LDT 40                  /* k-major tile row stride, elements */
#define LDW 136                 /* row-major-B tile row stride, elements (272B, 16B-aligned) */
#define TILEB (128 * LDT * 2)   /* 10240 B per operand tile slot */
#define STGB (2 * TILEB)        /* A+B per stage = 20480 B */
#define NSTG 3
#define SM_GEMM (NSTG * STGB)   /* 61440 B */

typedef wmma::fragment<wmma::matrix_a, 16, 16, 16, __nv_bfloat16, wmma::row_major> FragA;
typedef wmma::fragment<wmma::matrix_b, 16, 16, 16, __nv_bfloat16, wmma::col_major> FragB;
typedef wmma::fragment<wmma::matrix_b, 16, 16, 16, __nv_bfloat16, wmma::row_major> FragBR;
typedef wmma::fragment<wmma::accumulator, 16, 16, 16, float> FragC;

/* ---------------- scratch (no cudaMalloc allowed) ---------------- */
#define SZ_CN ((size_t)NB * CCH * HW)
#define SZ_EE ((size_t)NB * HW * HW)
static __device__ __align__(16) __nv_bfloat16 g_ex_h[SZ_CN], g_ex_l[SZ_CN];   /* in1 [b][c][n] */
static __device__ __align__(16) __nv_bfloat16 g_q_h[SZ_CN],  g_q_l[SZ_CN];    /* in2 [b][c][m] */
static __device__ __align__(16) __nv_bfloat16 g_ext_h[SZ_CN], g_ext_l[SZ_CN]; /* in1^T [b][x][c] */
static __device__ __align__(16) __nv_bfloat16 g_qt_h[SZ_CN],  g_qt_l[SZ_CN];  /* in2^T [b][x][c] */
static __device__ __align__(16) __nv_bfloat16 g_We_h[CCH*CCH], g_We_l[CCH*CCH];
static __device__ __align__(16) __nv_bfloat16 g_W1_h[CCH*2*CCH], g_W1_l[CCH*2*CCH];
static __device__ __align__(16) __nv_bfloat16 g_W2_h[CCH*2*CCH], g_W2_l[CCH*2*CCH];
static __device__ __align__(16) __nv_bfloat16 g_ec_h[SZ_CN], g_ec_l[SZ_CN];   /* [b][n][d] */
static __device__ __align__(16) __nv_bfloat16 g_En_h[SZ_EE], g_En_l[SZ_EE];   /* E [b][n][m] */
static __device__ __align__(16) __nv_bfloat16 g_qatt_h[SZ_CN], g_qatt_l[SZ_CN]; /* gated [b][m][c] */
static __device__ __align__(16) __nv_bfloat16 g_eatt_h[SZ_CN], g_eatt_l[SZ_CN]; /* gated [b][n][c] */
static __device__ __align__(16) float g_qattF[SZ_CN], g_eattF[SZ_CN];
static __device__ float g_colsum[NB*HW], g_rowsum[NB*HW];

__device__ __forceinline__ uint32_t s2u(const void* p) {
    uint32_t a;
    asm("{ .reg .u64 t; cvta.to.shared.u64 t, %1; cvt.u32.u64 %0, t; }" : "=r"(a) : "l"(p));
    return a;
}
__device__ __forceinline__ void cpa16(uint32_t d, const void* g) {
    asm volatile("cp.async.cg.shared.global [%0], [%1], 16;" :: "r"(d), "l"(g));
}

/* ============ wmma 128x128 GEMM core: 3-pass split-bf16, 3-stage cp.async ============ */
/* BROW=0: C[r][c] = sum_k A[r][k]*B[c][k] (B k-major).                                  */
/* BROW=1: C[r][c] = sum_k A[r][k]*B[k][c] (B row-major [k][c], ldb = global row stride).*/
template <bool BROW>
__device__ void gemm_core(char* sm, uint32_t smu,
    const __nv_bfloat16* Ah, const __nv_bfloat16* Al, int lda,
    const __nv_bfloat16* B1h, const __nv_bfloat16* B1l,
    const __nv_bfloat16* B2h, const __nv_bfloat16* B2l, int ksplit, int ldb,
    int K, FragC (&acc)[2][4])
{
    const int t = threadIdx.x, wid = t >> 5;
    const int wm = wid >> 1, wn = wid & 1;  /* 4x2 warps: 32-row x 64-col per warp */
    const int nch = K / 32, total = nch * 3;

#pragma unroll
    for (int mf = 0; mf < 2; ++mf)
#pragma unroll
        for (int nf = 0; nf < 4; ++nf)
            wmma::fill_fragment(acc[mf][nf], 0.0f);

    auto src = [&](int it, const __nv_bfloat16*& A, const __nv_bfloat16*& B) {
        int p = it / nch, k0 = (it - p * nch) * 32;
        A = ((p == 2) ? Al : Ah) + k0;
        const __nv_bfloat16* bh = B1h; const __nv_bfloat16* bl = B1l; int kb = k0;
        if (k0 >= ksplit) { bh = B2h; bl = B2l; kb = k0 - ksplit; }
        const __nv_bfloat16* bb = (p == 1) ? bl : bh;
        B = BROW ? bb + (size_t)kb * ldb : bb + kb;
    };
    auto issue = [&](int it) {
        const __nv_bfloat16 *A, *B;
        src(it, A, B);
        uint32_t buf = (uint32_t)(it % NSTG) * STGB;
#pragma unroll
        for (int i = 0; i < 2; ++i) {
            int v = t * 2 + i;
            { int r = v >> 2, c = v & 3;
              cpa16(smu + buf + r * (LDT * 2) + c * 16, A + (size_t)r * lda + c * 8); }
            if (BROW) {
                int r = v >> 4, c = v & 15;
                cpa16(smu + buf + TILEB + r * (LDW * 2) + c * 16, B + (size_t)r * ldb + c * 8);
            } else {
                int r = v >> 2, c = v & 3;
                cpa16(smu + buf + TILEB + r * (LDT * 2) + c * 16, B + (size_t)r * ldb + c * 8);
            }
        }
        asm volatile("cp.async.commit_group;" ::: "memory");
    };
    auto comp = [&](int stg) {
        const __nv_bfloat16* As = (const __nv_bfloat16*)(sm + stg * STGB);
        const __nv_bfloat16* Bs = (const __nv_bfloat16*)(sm + stg * STGB + TILEB);
#pragma unroll
        for (int kk = 0; kk < 32; kk += 16) {
            FragA af[2];
#pragma unroll
            for (int mf = 0; mf < 2; ++mf)
                wmma::load_matrix_sync(af[mf], As + (wm * 32 + mf * 16) * LDT + kk, LDT);
            if (BROW) {
                FragBR bfr[4];
#pragma unroll
                for (int nf = 0; nf < 4; ++nf)
                    wmma::load_matrix_sync(bfr[nf], Bs + kk * LDW + wn * 64 + nf * 16, LDW);
#pragma unroll
                for (int mf = 0; mf < 2; ++mf)
#pragma unroll
                    for (int nf = 0; nf < 4; ++nf)
                        wmma::mma_sync(acc[mf][nf], af[mf], bfr[nf], acc[mf][nf]);
            } else {
                FragB bfr[4];
#pragma unroll
                for (int nf = 0; nf < 4; ++nf)
                    wmma::load_matrix_sync(bfr[nf], Bs + (wn * 64 + nf * 16) * LDT + kk, LDT);
#pragma unroll
                for (int mf = 0; mf < 2; ++mf)
#pragma unroll
                    for (int nf = 0; nf < 4; ++nf)
                        wmma::mma_sync(acc[mf][nf], af[mf], bfr[nf], acc[mf][nf]);
            }
        }
    };

    issue(0);
    if (total > 1) issue(1);
    for (int it = 0; it < total; ++it) {
        if (it + 1 < total)
            asm volatile("cp.async.wait_group 1;" ::: "memory");
        else
            asm volatile("cp.async.wait_group 0;" ::: "memory");
        __syncthreads();
        if (it + 2 < total) issue(it + 2);
        comp(it % NSTG);
    }
}

__device__ __forceinline__ void store_c(FragC (&acc)[2][4], float* C, int ldc)
{
    int wid = threadIdx.x >> 5, wm = wid >> 1, wn = wid & 1;
#pragma unroll
    for (int mf = 0; mf < 2; ++mf)
#pragma unroll
        for (int nf = 0; nf < 4; ++nf)
            wmma::store_matrix_sync(C + (size_t)(wm * 32 + mf * 16) * ldc + wn * 64 + nf * 16,
                                    acc[mf][nf], ldc, wmma::mem_row_major);
}
__device__ __forceinline__ void store_c_col(FragC (&acc)[2][4], float* C, int ldc)
{
    /* element (r,c) of the 128x128 tile -> C[c*ldc + r] */
    int wid = threadIdx.x >> 5, wm = wid >> 1, wn = wid & 1;
#pragma unroll
    for (int mf = 0; mf < 2; ++mf)
#pragma unroll
        for (int nf = 0; nf < 4; ++nf)
            wmma::store_matrix_sync(C + (size_t)(wn * 64 + nf * 16) * ldc + wm * 32 + mf * 16,
                                    acc[mf][nf], ldc, wmma::mem_col_major);
}

/* ---- shared epilogue: stage acc halves (64 rows each), write hi/lo split ---- */
__device__ void epilogue_split(char* sm, FragC (&acc)[2][4],
    __nv_bfloat16* dh, __nv_bfloat16* dl, size_t rowbase, int ldo)
{
    int t = threadIdx.x, wid = t >> 5, wm = wid >> 1, wn = wid & 1;
    float* stg = (float*)sm;
    const int LDS2 = 132;
    for (int h = 0; h < 2; ++h) {
        __syncthreads();
        if ((wm >> 1) == h) {
            int lm = wm & 1;
#pragma unroll
            for (int mf = 0; mf < 2; ++mf)
#pragma unroll
                for (int nf = 0; nf < 4; ++nf)
                    wmma::store_matrix_sync(stg + (lm * 32 + mf * 16) * LDS2 + wn * 64 + nf * 16,
                                            acc[mf][nf], LDS2, wmma::mem_row_major);
        }
        __syncthreads();
        int row = t >> 2, seg = t & 3;        /* 64 rows x 4 segments of 32 */
        const float* sp = stg + row * LDS2 + seg * 32;
        size_t o = rowbase + (size_t)(h * 64 + row) * ldo + seg * 32;
#pragma unroll
        for (int q = 0; q < 4; ++q) {
            __nv_bfloat162 hv[4], lv[4];
#pragma unroll
            for (int j = 0; j < 4; ++j) {
                float a = sp[q * 8 + 2 * j], c2 = sp[q * 8 + 2 * j + 1];
                __nv_bfloat16 ha = __float2bfloat16(a), hc = __float2bfloat16(c2);
                hv[j].x = ha; hv[j].y = hc;
                lv[j].x = __float2bfloat16(a - __bfloat162float(ha));
                lv[j].y = __float2bfloat16(c2 - __bfloat162float(hc));
            }
            *(uint4*)(dh + o + q * 8) = *(uint4*)hv;
            *(uint4*)(dl + o + q * 8) = *(uint4*)lv;
        }
    }
}

/* ---------------- GEMM1: ec[n][d] (hi/lo) = ext[n][:] . We[d][:] ---------------- */
__global__ __launch_bounds__(256, 2) void k_g1()
{
    extern __shared__ __align__(128) char sm[];
    uint32_t smu = s2u(sm);
    int b = blockIdx.z, r0 = blockIdx.y * 128, c0 = blockIdx.x * 128;
    FragC acc[2][4];
    size_t ao = ((size_t)b * HW + r0) * CCH;
    gemm_core<false>(sm, smu, g_ext_h + ao, g_ext_l + ao, CCH,
              g_We_h + (size_t)c0 * CCH, g_We_l + (size_t)c0 * CCH,
              g_We_h + (size_t)c0 * CCH, g_We_l + (size_t)c0 * CCH, 1 << 30, CCH, CCH, acc);
    epilogue_split(sm, acc, g_ec_h, g_ec_l, ao + c0, CCH);
}

/* ---- GEMM2 + fused epilogue: E=__expf(ec.qt^T); En[n][m] hi/lo; row/col sums ---- */
__global__ __launch_bounds__(256, 2) void k_g2()
{
    extern __shared__ __align__(128) char sm[];
    uint32_t smu = s2u(sm);
    int b = blockIdx.z, r0 = blockIdx.y * 128, c0 = blockIdx.x * 128; /* r=n, c=m */
    int t = threadIdx.x, wid = t >> 5, wm = wid >> 1, wn = wid & 1;
    FragC acc[2][4];
    size_t ao = ((size_t)b * HW + r0) * CCH, bo = ((size_t)b * HW + c0) * CCH;
    gemm_core<false>(sm, smu, g_ec_h + ao, g_ec_l + ao, CCH,
              g_qt_h + bo, g_qt_l + bo, g_qt_h + bo, g_qt_l + bo, 1 << 30, CCH, CCH, acc);

#pragma unroll
    for (int mf = 0; mf < 2; ++mf)
#pragma unroll
        for (int nf = 0; nf < 4; ++nf)
#pragma unroll
            for (int i = 0; i < acc[mf][nf].num_elements; ++i)
                acc[mf][nf].x[i] = __expf(acc[mf][nf].x[i]);

    float* stg = (float*)sm;
    const int LDS2 = 132;
    for (int h = 0; h < 2; ++h) {
        __syncthreads();
        if ((wm >> 1) == h) {
            int lm = wm & 1;
#pragma unroll
            for (int mf = 0; mf < 2; ++mf)
#pragma unroll
                for (int nf = 0; nf < 4; ++nf)
                    wmma::store_matrix_sync(stg + (lm * 32 + mf * 16) * LDS2 + wn * 64 + nf * 16,
                                            acc[mf][nf], LDS2, wmma::mem_row_major);
        }
        __syncthreads();
        /* En rows + rowsum */
        {
            int row = t >> 2, seg = t & 3;
            const float* sp = stg + row * LDS2 + seg * 32;
            size_t o = ((size_t)b * HW + r0 + h * 64 + row) * HW + c0 + seg * 32;
            float rs = 0.f;
#pragma unroll
            for (int q = 0; q < 4; ++q) {
                __nv_bfloat162 hv[4], lv[4];
#pragma unroll
                for (int j = 0; j < 4; ++j) {
                    float a = sp[q * 8 + 2 * j], c2 = sp[q * 8 + 2 * j + 1];
                    rs += a + c2;
                    __nv_bfloat16 ha = __float2bfloat16(a), hc = __float2bfloat16(c2);
                    hv[j].x = ha; hv[j].y = hc;
                    lv[j].x = __float2bfloat16(a - __bfloat162float(ha));
                    lv[j].y = __float2bfloat16(c2 - __bfloat162float(hc));
                }
                *(uint4*)(g_En_h + o + q * 8) = *(uint4*)hv;
                *(uint4*)(g_En_l + o + q * 8) = *(uint4*)lv;
            }
            rs += __shfl_xor_sync(~0u, rs, 1);
            rs += __shfl_xor_sync(~0u, rs, 2);
            if (seg == 0) atomicAdd(&g_rowsum[b * HW + r0 + h * 64 + row], rs);
        }
        /* colsum via strided smem reads (no transposed global store) */
        {
            int col = t >> 1, rh = t & 1;
            const float* sp = stg + (rh * 32) * LDS2 + col;
            float cs = 0.f;
#pragma unroll
            for (int j = 0; j < 32; ++j) cs += sp[j * LDS2];
            cs += __shfl_xor_sync(~0u, cs, 1);
            if (rh == 0) atomicAdd(&g_colsum[b * HW + c0 + col], cs);
        }
    }
}

/* ------ GEMM3/4 merged (both read only En): z -> (b, sel) ------ */
__global__ __launch_bounds__(256, 2) void k_att()
{
    extern __shared__ __align__(128) char sm[];
    uint32_t smu = s2u(sm);
    int z = blockIdx.z, b = z >> 1, sel = z & 1;
    FragC acc[2][4];
    if (sel == 1) {
        /* eattF[n][c] = sum_m En[n][m] q[c][m] */
        int r0 = blockIdx.y * 128, c0 = blockIdx.x * 128;
        size_t ao = ((size_t)b * HW + r0) * HW, bo = ((size_t)b * CCH + c0) * HW;
        gemm_core<false>(sm, smu, g_En_h + ao, g_En_l + ao, HW,
                  g_q_h + bo, g_q_l + bo, g_q_h + bo, g_q_l + bo, 1 << 30, HW, HW, acc);
        __syncthreads();
        store_c(acc, g_eattF + ((size_t)b * HW + r0) * CCH + c0, CCH);
    } else {
        /* C[c][m] = sum_n ex[c][n] En[n][m]; stored col-major -> qattF[m][c] */
        int cblk = blockIdx.x * 128, m0 = blockIdx.y * 128;
        size_t ao = ((size_t)b * CCH + cblk) * HW;
        const __nv_bfloat16* Bh = g_En_h + (size_t)b * HW * HW + m0;
        const __nv_bfloat16* Bl = g_En_l + (size_t)b * HW * HW + m0;
        gemm_core<true>(sm, smu, g_ex_h + ao, g_ex_l + ao, HW,
                  Bh, Bl, Bh, Bl, 1 << 30, HW, HW, acc);
        __syncthreads();
        store_c_col(acc, g_qattF + ((size_t)b * HW + m0) * CCH + cblk, CCH);
    }
}

/* ------ conv merged: out[o][x] = W[o][0:512].[att|inp_t][x][0:512]; z -> (b, w) ------ */
__global__ __launch_bounds__(256, 2) void k_conv(float* __restrict__ out)
{
    extern __shared__ __align__(128) char sm[];
    uint32_t smu = s2u(sm);
    int z = blockIdx.z, b = z >> 1, w = z & 1;
    int o0 = blockIdx.y * 128, x0 = blockIdx.x * 128;
    const __nv_bfloat16 *Wh, *Wl, *B1h, *B1l, *B2h, *B2l;
    if (w == 0) { Wh = g_W1_h; Wl = g_W1_l; B1h = g_eatt_h; B1l = g_eatt_l; B2h = g_ext_h; B2l = g_ext_l; }
    else        { Wh = g_W2_h; Wl = g_W2_l; B1h = g_qatt_h; B1l = g_qatt_l; B2h = g_qt_h;  B2l = g_qt_l; }
    FragC acc[2][4];
    size_t bo = ((size_t)b * HW + x0) * CCH;
    gemm_core<false>(sm, smu, Wh + (size_t)o0 * 512, Wl + (size_t)o0 * 512, 512,
              B1h + bo, B1l + bo, B2h + bo, B2l + bo, 256, CCH, 512, acc);
    __syncthreads();
    store_c(acc, out + (size_t)w * SZ_CN + ((size_t)b * CCH + o0) * HW + x0, HW);
}

/* ---------------- ew3 merged: normalize + gate + split; y -> sel ---------------- */
__global__ __launch_bounds__(256) void k_ew3(const float* __restrict__ gw)
{
    __shared__ float sgw[256];
    int tid = threadIdx.x, lane = tid & 31, wid = tid >> 5;
    int sel = blockIdx.y;
    sgw[tid] = gw[tid];
    __syncthreads();
    const float* af = sel ? g_eattF : g_qattF;
    const float* sums = sel ? g_rowsum : g_colsum;
    __nv_bfloat16* oh = sel ? g_eatt_h : g_qatt_h;
    __nv_bfloat16* ol = sel ? g_eatt_l : g_qatt_l;
    size_t row = (size_t)blockIdx.x * 8 + wid;
    float4 v0 = *(const float4*)(af + row * 256 + lane * 8);
    float4 v1 = *(const float4*)(af + row * 256 + lane * 8 + 4);
    float v[8] = {v0.x, v0.y, v0.z, v0.w, v1.x, v1.y, v1.z, v1.w};
    float dot = 0.f;
#pragma unroll
    for (int j = 0; j < 8; ++j) dot += v[j] * sgw[lane * 8 + j];
#pragma unroll
    for (int m = 16; m; m >>= 1) dot += __shfl_xor_sync(~0u, dot, m);
    float inv = 1.f / sums[row];
    float s = inv / (1.f + expf(-inv * dot));
    __nv_bfloat162 hq[4], lq[4];
#pragma unroll
    for (int j = 0; j < 4; ++j) {
        float a = v[2 * j] * s, c = v[2 * j + 1] * s;
        __nv_bfloat16 ha = __float2bfloat16(a), hc = __float2bfloat16(c);
        hq[j].x = ha; hq[j].y = hc;
        lq[j].x = __float2bfloat16(a - __bfloat162float(ha));
        lq[j].y = __float2bfloat16(c - __bfloat162float(hc));
    }
    *(uint4*)(oh + row * 256 + lane * 8) = *(uint4*)hq;
    *(uint4*)(ol + row * 256 + lane * 8) = *(uint4*)lq;
}

/* ---------------- prep1: ALL linear splits + zero, one launch ---------------- */
#define N2IN ((int)(SZ_CN / 2))                  /* 2097152 float2 per input */
__global__ void k_prep1(const float* __restrict__ in1, const float* __restrict__ in2,
                        const float* __restrict__ We, const float* __restrict__ W1,
                        const float* __restrict__ W2)
{
    int idx = blockIdx.x * 256 + threadIdx.x;
    const float* src; __nv_bfloat16 *dh, *dl; int i = idx;
    if (idx < N2IN)                         { src = in1; dh = g_ex_h; dl = g_ex_l; }
    else if ((i -= N2IN) < N2IN)            { src = in2; dh = g_q_h;  dl = g_q_l;  }
    else if ((i -= N2IN) < CCH*CCH/2)       { src = We;  dh = g_We_h; dl = g_We_l; }
    else if ((i -= CCH*CCH/2) < CCH*CCH)    { src = W1;  dh = g_W1_h; dl = g_W1_l; }
    else if ((i -= CCH*CCH) < CCH*CCH)      { src = W2;  dh = g_W2_h; dl = g_W2_l; }
    else {
        i -= CCH*CCH;
        if (i < NB * HW) { g_colsum[i] = 0.f; g_rowsum[i] = 0.f; }
        return;
    }
    float2 v = ((const float2*)src)[i];
    __nv_bfloat16 h0 = __float2bfloat16(v.x), h1 = __float2bfloat16(v.y);
    __nv_bfloat162 hp, lp;
    hp.x = h0; hp.y = h1;
    lp.x = __float2bfloat16(v.x - __bfloat162float(h0));
    lp.y = __float2bfloat16(v.y - __bfloat162float(h1));
    ((__nv_bfloat162*)dh)[i] = hp;
    ((__nv_bfloat162*)dl)[i] = lp;
}
#define PREP1_TOTAL (2 * N2IN + CCH*CCH/2 + 2 * CCH*CCH + NB * HW)

/* ---------------- tsplit both inputs: z = sel*NB + b ---------------- */
__global__ void k_tsplit(const float* __restrict__ in1, const float* __restrict__ in2)
{
    __shared__ float t[32][33];
    int z = blockIdx.z, sel = z / NB, b = z % NB;
    const float* src = sel ? in2 : in1;
    __nv_bfloat16* dh = sel ? g_qt_h : g_ext_h;
    __nv_bfloat16* dl = sel ? g_qt_l : g_ext_l;
    int c0 = blockIdx.y * 32, n0 = blockIdx.x * 32;
    int tx = threadIdx.x, ty = threadIdx.y;
#pragma unroll
    for (int i = 0; i < 4; ++i)
        t[ty + i * 8][tx] = src[((size_t)b * CCH + c0 + ty + i * 8) * HW + n0 + tx];
    __syncthreads();
#pragma unroll
    for (int i = 0; i < 4; ++i) {
        float v = t[tx][ty + i * 8];
        size_t o = ((size_t)b * HW + n0 + ty + i * 8) * CCH + c0 + tx;
        __nv_bfloat16 h = __float2bfloat16(v);
        dh[o] = h;
        dl[o] = __float2bfloat16(v - __bfloat162float(h));
    }
}

/* ---------------- launch ---------------- */
extern "C" void kernel_launch(void* const* d_in, const int* in_sizes, int n_in,
                              void* d_out, int out_size)
{
    const float* in1 = (const float*)d_in[0];
    const float* in2 = (const float*)d_in[1];
    const float* We  = (const float*)d_in[2];
    const float* gw  = (const float*)d_in[3];
    const float* W1  = (const float*)d_in[4];
    const float* W2  = (const float*)d_in[5];
    float* out = (float*)d_out;

    cudaFuncSetAttribute(k_g1,   cudaFuncAttributeMaxDynamicSharedMemorySize, SM_GEMM);
    cudaFuncSetAttribute(k_g2,   cudaFuncAttributeMaxDynamicSharedMemorySize, SM_GEMM);
    cudaFuncSetAttribute(k_att,  cudaFuncAttributeMaxDynamicSharedMemorySize, SM_GEMM);
    cudaFuncSetAttribute(k_conv, cudaFuncAttributeMaxDynamicSharedMemorySize, SM_GEMM);

    k_prep1<<<(PREP1_TOTAL + 255) / 256, 256>>>(in1, in2, We, W1, W2);           /* #1 */
    k_tsplit<<<dim3(HW / 32, CCH / 32, NB * 2), dim3(32, 8)>>>(in1, in2);        /* #2 */
    k_g1<<<dim3(CCH / 128, HW / 128, NB), 256, SM_GEMM>>>();                     /* #3 */
    k_g2<<<dim3(HW / 128, HW / 128, NB), 256, SM_GEMM>>>();                      /* #4 <- ncu */
    k_att<<<dim3(CCH / 128, HW / 128, NB * 2), 256, SM_GEMM>>>();                /* #5 */
    k_ew3<<<dim3(NB * HW / 8, 2), 256>>>(gw);                                    /* #6 */
    k_conv<<<dim3(HW / 128, CCH / 128, NB * 2), 256, SM_GEMM>>>(out);            /* #7 */
}

// round 14
// speedup vs baseline: 3.6877x; 1.2964x over previous
#include <cuda_runtime.h>
#include <cuda_bf16.h>
#include <mma.h>
#include <cstdint>
#include <math.h>

using namespace nvcuda;

#define NB 4
#define CCH 256
#define HW 4096

#define LDT 40                  /* k-major tile row stride, elements */
#define LDW 136                 /* row-major-B tile row stride, elements (272B) */
#define TILEA 10240             /* bytes per operand tile slot */
#define STGB (2 * TILEA)        /* A+B per stage = 20480 B */
#define NSTG 3
#define SM_GEMM (NSTG * STGB)   /* 61440 B */
#define NTHR 128

typedef wmma::fragment<wmma::matrix_a, 16, 16, 16, __nv_bfloat16, wmma::row_major> FragA;
typedef wmma::fragment<wmma::matrix_b, 16, 16, 16, __nv_bfloat16, wmma::col_major> FragB;
typedef wmma::fragment<wmma::matrix_b, 16, 16, 16, __nv_bfloat16, wmma::row_major> FragBR;
typedef wmma::fragment<wmma::accumulator, 16, 16, 16, float> FragC;

/* ---------------- scratch (no cudaMalloc allowed) ---------------- */
#define SZ_CN ((size_t)NB * CCH * HW)
#define SZ_EE ((size_t)NB * HW * HW)
static __device__ __align__(16) __nv_bfloat16 g_ex_h[SZ_CN], g_ex_l[SZ_CN];
static __device__ __align__(16) __nv_bfloat16 g_q_h[SZ_CN],  g_q_l[SZ_CN];
static __device__ __align__(16) __nv_bfloat16 g_ext_h[SZ_CN], g_ext_l[SZ_CN];
static __device__ __align__(16) __nv_bfloat16 g_qt_h[SZ_CN],  g_qt_l[SZ_CN];
static __device__ __align__(16) __nv_bfloat16 g_We_h[CCH*CCH], g_We_l[CCH*CCH];
static __device__ __align__(16) __nv_bfloat16 g_W1_h[CCH*2*CCH], g_W1_l[CCH*2*CCH];
static __device__ __align__(16) __nv_bfloat16 g_W2_h[CCH*2*CCH], g_W2_l[CCH*2*CCH];
static __device__ __align__(16) __nv_bfloat16 g_ec_h[SZ_CN], g_ec_l[SZ_CN];
static __device__ __align__(16) __nv_bfloat16 g_En_h[SZ_EE], g_En_l[SZ_EE];
static __device__ __align__(16) __nv_bfloat16 g_qatt_h[SZ_CN], g_qatt_l[SZ_CN];
static __device__ __align__(16) __nv_bfloat16 g_eatt_h[SZ_CN], g_eatt_l[SZ_CN];
static __device__ __align__(16) float g_qattF[SZ_CN], g_eattF[SZ_CN];
static __device__ float g_colsum[NB*HW], g_rowsum[NB*HW];

__device__ __forceinline__ uint32_t s2u(const void* p) {
    uint32_t a;
    asm("{ .reg .u64 t; cvta.to.shared.u64 t, %1; cvt.u32.u64 %0, t; }" : "=r"(a) : "l"(p));
    return a;
}
__device__ __forceinline__ void cpa16(uint32_t d, const void* g) {
    asm volatile("cp.async.cg.shared.global [%0], [%1], 16;" :: "r"(d), "l"(g));
}

/* ==== wmma 128x128 GEMM core: 4 warps, 64x64 warp tiles, 3-pass split-bf16, 3-stage ==== */
template <bool BROW>
__device__ void gemm_core(char* sm, uint32_t smu,
    const __nv_bfloat16* Ah, const __nv_bfloat16* Al, int lda,
    const __nv_bfloat16* B1h, const __nv_bfloat16* B1l,
    const __nv_bfloat16* B2h, const __nv_bfloat16* B2l, int ksplit, int ldb,
    int K, FragC (&acc)[4][4])
{
    const int t = threadIdx.x, wid = t >> 5;
    const int wm = wid >> 1, wn = wid & 1;  /* 2x2 warps: 64x64 tile each */
    const int nch = K / 32, total = nch * 3;

#pragma unroll
    for (int mf = 0; mf < 4; ++mf)
#pragma unroll
        for (int nf = 0; nf < 4; ++nf)
            wmma::fill_fragment(acc[mf][nf], 0.0f);

    auto src = [&](int it, const __nv_bfloat16*& A, const __nv_bfloat16*& B) {
        int p = it / nch, k0 = (it - p * nch) * 32;
        A = ((p == 2) ? Al : Ah) + k0;
        const __nv_bfloat16* bh = B1h; const __nv_bfloat16* bl = B1l; int kb = k0;
        if (k0 >= ksplit) { bh = B2h; bl = B2l; kb = k0 - ksplit; }
        const __nv_bfloat16* bb = (p == 1) ? bl : bh;
        B = BROW ? bb + (size_t)kb * ldb : bb + kb;
    };
    auto issue = [&](int it) {
        const __nv_bfloat16 *A, *B;
        src(it, A, B);
        uint32_t buf = (uint32_t)(it % NSTG) * STGB;
#pragma unroll
        for (int i = 0; i < 4; ++i) {
            int v = t + i * NTHR;
            { int r = v >> 2, c = v & 3;
              cpa16(smu + buf + r * (LDT * 2) + c * 16, A + (size_t)r * lda + c * 8); }
            if (BROW) {
                int r = v >> 4, c = v & 15;
                cpa16(smu + buf + TILEA + r * (LDW * 2) + c * 16, B + (size_t)r * ldb + c * 8);
            } else {
                int r = v >> 2, c = v & 3;
                cpa16(smu + buf + TILEA + r * (LDT * 2) + c * 16, B + (size_t)r * ldb + c * 8);
            }
        }
        asm volatile("cp.async.commit_group;" ::: "memory");
    };
    auto comp = [&](int stg) {
        const __nv_bfloat16* As = (const __nv_bfloat16*)(sm + stg * STGB);
        const __nv_bfloat16* Bs = (const __nv_bfloat16*)(sm + stg * STGB + TILEA);
#pragma unroll
        for (int kk = 0; kk < 32; kk += 16) {
            FragA af[4];
#pragma unroll
            for (int mf = 0; mf < 4; ++mf)
                wmma::load_matrix_sync(af[mf], As + (wm * 64 + mf * 16) * LDT + kk, LDT);
            if (BROW) {
                FragBR bfr[4];
#pragma unroll
                for (int nf = 0; nf < 4; ++nf)
                    wmma::load_matrix_sync(bfr[nf], Bs + kk * LDW + wn * 64 + nf * 16, LDW);
#pragma unroll
                for (int mf = 0; mf < 4; ++mf)
#pragma unroll
                    for (int nf = 0; nf < 4; ++nf)
                        wmma::mma_sync(acc[mf][nf], af[mf], bfr[nf], acc[mf][nf]);
            } else {
                FragB bfr[4];
#pragma unroll
                for (int nf = 0; nf < 4; ++nf)
                    wmma::load_matrix_sync(bfr[nf], Bs + (wn * 64 + nf * 16) * LDT + kk, LDT);
#pragma unroll
                for (int mf = 0; mf < 4; ++mf)
#pragma unroll
                    for (int nf = 0; nf < 4; ++nf)
                        wmma::mma_sync(acc[mf][nf], af[mf], bfr[nf], acc[mf][nf]);
            }
        }
    };

    issue(0);
    if (total > 1) issue(1);
    for (int it = 0; it < total; ++it) {
        if (it + 1 < total)
            asm volatile("cp.async.wait_group 1;" ::: "memory");
        else
            asm volatile("cp.async.wait_group 0;" ::: "memory");
        __syncthreads();
        if (it + 2 < total) issue(it + 2);   /* writes stage (it+2)%3 = (it-1)%3: free */
        comp(it % NSTG);
    }
}

__device__ __forceinline__ void store_c(FragC (&acc)[4][4], float* C, int ldc)
{
    int wid = threadIdx.x >> 5, wm = wid >> 1, wn = wid & 1;
#pragma unroll
    for (int mf = 0; mf < 4; ++mf)
#pragma unroll
        for (int nf = 0; nf < 4; ++nf)
            wmma::store_matrix_sync(C + (size_t)(wm * 64 + mf * 16) * ldc + wn * 64 + nf * 16,
                                    acc[mf][nf], ldc, wmma::mem_row_major);
}
__device__ __forceinline__ void store_c_col(FragC (&acc)[4][4], float* C, int ldc)
{
    int wid = threadIdx.x >> 5, wm = wid >> 1, wn = wid & 1;
#pragma unroll
    for (int mf = 0; mf < 4; ++mf)
#pragma unroll
        for (int nf = 0; nf < 4; ++nf)
            wmma::store_matrix_sync(C + (size_t)(wn * 64 + nf * 16) * ldc + wm * 64 + mf * 16,
                                    acc[mf][nf], ldc, wmma::mem_col_major);
}

/* ---- epilogue: stage 64-row halves, write hi/lo split, 128 threads ---- */
__device__ void epilogue_split(char* sm, FragC (&acc)[4][4],
    __nv_bfloat16* dh, __nv_bfloat16* dl, size_t rowbase, int ldo)
{
    int t = threadIdx.x, wid = t >> 5, wm = wid >> 1, wn = wid & 1;
    float* stg = (float*)sm;
    const int LDS2 = 132;
    for (int h = 0; h < 2; ++h) {
        __syncthreads();
        if (wm == h) {
#pragma unroll
            for (int mf = 0; mf < 4; ++mf)
#pragma unroll
                for (int nf = 0; nf < 4; ++nf)
                    wmma::store_matrix_sync(stg + (mf * 16) * LDS2 + wn * 64 + nf * 16,
                                            acc[mf][nf], LDS2, wmma::mem_row_major);
        }
        __syncthreads();
        int row = t >> 1, seg = t & 1;        /* 64 rows x 2 segments of 64 */
        const float* sp = stg + row * LDS2 + seg * 64;
        size_t o = rowbase + (size_t)(h * 64 + row) * ldo + seg * 64;
#pragma unroll
        for (int q = 0; q < 8; ++q) {
            __nv_bfloat162 hv[4], lv[4];
#pragma unroll
            for (int j = 0; j < 4; ++j) {
                float a = sp[q * 8 + 2 * j], c2 = sp[q * 8 + 2 * j + 1];
                __nv_bfloat16 ha = __float2bfloat16(a), hc = __float2bfloat16(c2);
                hv[j].x = ha; hv[j].y = hc;
                lv[j].x = __float2bfloat16(a - __bfloat162float(ha));
                lv[j].y = __float2bfloat16(c2 - __bfloat162float(hc));
            }
            *(uint4*)(dh + o + q * 8) = *(uint4*)hv;
            *(uint4*)(dl + o + q * 8) = *(uint4*)lv;
        }
    }
}

/* ---------------- GEMM1: ec[n][d] (hi/lo) = ext[n][:] . We[d][:] ---------------- */
__global__ __launch_bounds__(NTHR, 2) void k_g1()
{
    extern __shared__ __align__(128) char sm[];
    uint32_t smu = s2u(sm);
    int b = blockIdx.z, r0 = blockIdx.y * 128, c0 = blockIdx.x * 128;
    FragC acc[4][4];
    size_t ao = ((size_t)b * HW + r0) * CCH;
    gemm_core<false>(sm, smu, g_ext_h + ao, g_ext_l + ao, CCH,
              g_We_h + (size_t)c0 * CCH, g_We_l + (size_t)c0 * CCH,
              g_We_h + (size_t)c0 * CCH, g_We_l + (size_t)c0 * CCH, 1 << 30, CCH, CCH, acc);
    epilogue_split(sm, acc, g_ec_h, g_ec_l, ao + c0, CCH);
}

/* ---- GEMM2 + fused epilogue: E=__expf(ec.qt^T); En hi/lo; row/col sums ---- */
__global__ __launch_bounds__(NTHR, 2) void k_g2()
{
    extern __shared__ __align__(128) char sm[];
    uint32_t smu = s2u(sm);
    int b = blockIdx.z, r0 = blockIdx.y * 128, c0 = blockIdx.x * 128; /* r=n, c=m */
    int t = threadIdx.x, wid = t >> 5, wm = wid >> 1, wn = wid & 1;
    FragC acc[4][4];
    size_t ao = ((size_t)b * HW + r0) * CCH, bo = ((size_t)b * HW + c0) * CCH;
    gemm_core<false>(sm, smu, g_ec_h + ao, g_ec_l + ao, CCH,
              g_qt_h + bo, g_qt_l + bo, g_qt_h + bo, g_qt_l + bo, 1 << 30, CCH, CCH, acc);

#pragma unroll
    for (int mf = 0; mf < 4; ++mf)
#pragma unroll
        for (int nf = 0; nf < 4; ++nf)
#pragma unroll
            for (int i = 0; i < acc[mf][nf].num_elements; ++i)
                acc[mf][nf].x[i] = __expf(acc[mf][nf].x[i]);

    float* stg = (float*)sm;
    const int LDS2 = 132;
    float csum = 0.f;
    for (int h = 0; h < 2; ++h) {
        __syncthreads();
        if (wm == h) {
#pragma unroll
            for (int mf = 0; mf < 4; ++mf)
#pragma unroll
                for (int nf = 0; nf < 4; ++nf)
                    wmma::store_matrix_sync(stg + (mf * 16) * LDS2 + wn * 64 + nf * 16,
                                            acc[mf][nf], LDS2, wmma::mem_row_major);
        }
        __syncthreads();
        /* En rows + rowsum: 64 rows x 2 segs of 64 */
        {
            int row = t >> 1, seg = t & 1;
            const float* sp = stg + row * LDS2 + seg * 64;
            size_t o = ((size_t)b * HW + r0 + h * 64 + row) * HW + c0 + seg * 64;
            float rs = 0.f;
#pragma unroll
            for (int q = 0; q < 8; ++q) {
                __nv_bfloat162 hv[4], lv[4];
#pragma unroll
                for (int j = 0; j < 4; ++j) {
                    float a = sp[q * 8 + 2 * j], c2 = sp[q * 8 + 2 * j + 1];
                    rs += a + c2;
                    __nv_bfloat16 ha = __float2bfloat16(a), hc = __float2bfloat16(c2);
                    hv[j].x = ha; hv[j].y = hc;
                    lv[j].x = __float2bfloat16(a - __bfloat162float(ha));
                    lv[j].y = __float2bfloat16(c2 - __bfloat162float(hc));
                }
                *(uint4*)(g_En_h + o + q * 8) = *(uint4*)hv;
                *(uint4*)(g_En_l + o + q * 8) = *(uint4*)lv;
            }
            rs += __shfl_xor_sync(~0u, rs, 1);
            if (seg == 0) atomicAdd(&g_rowsum[b * HW + r0 + h * 64 + row], rs);
        }
        /* colsum: thread t owns column t, sums all 64 staged rows */
        {
            const float* sp = stg + t;
#pragma unroll
            for (int j = 0; j < 64; ++j) csum += sp[j * LDS2];
        }
    }
    atomicAdd(&g_colsum[b * HW + c0 + t], csum);
}

/* ------ GEMM3/4 merged (both read only En): z -> (b, sel) ------ */
__global__ __launch_bounds__(NTHR, 2) void k_att()
{
    extern __shared__ __align__(128) char sm[];
    uint32_t smu = s2u(sm);
    int z = blockIdx.z, b = z >> 1, sel = z & 1;
    FragC acc[4][4];
    if (sel == 1) {
        int r0 = blockIdx.y * 128, c0 = blockIdx.x * 128;
        size_t ao = ((size_t)b * HW + r0) * HW, bo = ((size_t)b * CCH + c0) * HW;
        gemm_core<false>(sm, smu, g_En_h + ao, g_En_l + ao, HW,
                  g_q_h + bo, g_q_l + bo, g_q_h + bo, g_q_l + bo, 1 << 30, HW, HW, acc);
        __syncthreads();
        store_c(acc, g_eattF + ((size_t)b * HW + r0) * CCH + c0, CCH);
    } else {
        int cblk = blockIdx.x * 128, m0 = blockIdx.y * 128;
        size_t ao = ((size_t)b * CCH + cblk) * HW;
        const __nv_bfloat16* Bh = g_En_h + (size_t)b * HW * HW + m0;
        const __nv_bfloat16* Bl = g_En_l + (size_t)b * HW * HW + m0;
        gemm_core<true>(sm, smu, g_ex_h + ao, g_ex_l + ao, HW,
                  Bh, Bl, Bh, Bl, 1 << 30, HW, HW, acc);
        __syncthreads();
        store_c_col(acc, g_qattF + ((size_t)b * HW + m0) * CCH + cblk, CCH);
    }
}

/* ------ conv merged: out[o][x] = W[o][0:512].[att|inp_t][x][0:512]; z -> (b, w) ------ */
__global__ __launch_bounds__(NTHR, 2) void k_conv(float* __restrict__ out)
{
    extern __shared__ __align__(128) char sm[];
    uint32_t smu = s2u(sm);
    int z = blockIdx.z, b = z >> 1, w = z & 1;
    int o0 = blockIdx.y * 128, x0 = blockIdx.x * 128;
    const __nv_bfloat16 *Wh, *Wl, *B1h, *B1l, *B2h, *B2l;
    if (w == 0) { Wh = g_W1_h; Wl = g_W1_l; B1h = g_eatt_h; B1l = g_eatt_l; B2h = g_ext_h; B2l = g_ext_l; }
    else        { Wh = g_W2_h; Wl = g_W2_l; B1h = g_qatt_h; B1l = g_qatt_l; B2h = g_qt_h;  B2l = g_qt_l; }
    FragC acc[4][4];
    size_t bo = ((size_t)b * HW + x0) * CCH;
    gemm_core<false>(sm, smu, Wh + (size_t)o0 * 512, Wl + (size_t)o0 * 512, 512,
              B1h + bo, B1l + bo, B2h + bo, B2l + bo, 256, CCH, 512, acc);
    __syncthreads();
    store_c(acc, out + (size_t)w * SZ_CN + ((size_t)b * CCH + o0) * HW + x0, HW);
}

/* ---------------- ew3 merged: normalize + gate + split; y -> sel ---------------- */
__global__ __launch_bounds__(256) void k_ew3(const float* __restrict__ gw)
{
    __shared__ float sgw[256];
    int tid = threadIdx.x, lane = tid & 31, wid = tid >> 5;
    int sel = blockIdx.y;
    sgw[tid] = gw[tid];
    __syncthreads();
    const float* af = sel ? g_eattF : g_qattF;
    const float* sums = sel ? g_rowsum : g_colsum;
    __nv_bfloat16* oh = sel ? g_eatt_h : g_qatt_h;
    __nv_bfloat16* ol = sel ? g_eatt_l : g_qatt_l;
    size_t row = (size_t)blockIdx.x * 8 + wid;
    float4 v0 = *(const float4*)(af + row * 256 + lane * 8);
    float4 v1 = *(const float4*)(af + row * 256 + lane * 8 + 4);
    float v[8] = {v0.x, v0.y, v0.z, v0.w, v1.x, v1.y, v1.z, v1.w};
    float dot = 0.f;
#pragma unroll
    for (int j = 0; j < 8; ++j) dot += v[j] * sgw[lane * 8 + j];
#pragma unroll
    for (int m = 16; m; m >>= 1) dot += __shfl_xor_sync(~0u, dot, m);
    float inv = 1.f / sums[row];
    float s = inv / (1.f + expf(-inv * dot));
    __nv_bfloat162 hq[4], lq[4];
#pragma unroll
    for (int j = 0; j < 4; ++j) {
        float a = v[2 * j] * s, c = v[2 * j + 1] * s;
        __nv_bfloat16 ha = __float2bfloat16(a), hc = __float2bfloat16(c);
        hq[j].x = ha; hq[j].y = hc;
        lq[j].x = __float2bfloat16(a - __bfloat162float(ha));
        lq[j].y = __float2bfloat16(c - __bfloat162float(hc));
    }
    *(uint4*)(oh + row * 256 + lane * 8) = *(uint4*)hq;
    *(uint4*)(ol + row * 256 + lane * 8) = *(uint4*)lq;
}

/* ---------------- prep1: ALL linear splits + zero, one launch ---------------- */
#define N2IN ((int)(SZ_CN / 2))
__global__ void k_prep1(const float* __restrict__ in1, const float* __restrict__ in2,
                        const float* __restrict__ We, const float* __restrict__ W1,
                        const float* __restrict__ W2)
{
    int idx = blockIdx.x * 256 + threadIdx.x;
    const float* src; __nv_bfloat16 *dh, *dl; int i = idx;
    if (idx < N2IN)                         { src = in1; dh = g_ex_h; dl = g_ex_l; }
    else if ((i -= N2IN) < N2IN)            { src = in2; dh = g_q_h;  dl = g_q_l;  }
    else if ((i -= N2IN) < CCH*CCH/2)       { src = We;  dh = g_We_h; dl = g_We_l; }
    else if ((i -= CCH*CCH/2) < CCH*CCH)    { src = W1;  dh = g_W1_h; dl = g_W1_l; }
    else if ((i -= CCH*CCH) < CCH*CCH)      { src = W2;  dh = g_W2_h; dl = g_W2_l; }
    else {
        i -= CCH*CCH;
        if (i < NB * HW) { g_colsum[i] = 0.f; g_rowsum[i] = 0.f; }
        return;
    }
    float2 v = ((const float2*)src)[i];
    __nv_bfloat16 h0 = __float2bfloat16(v.x), h1 = __float2bfloat16(v.y);
    __nv_bfloat162 hp, lp;
    hp.x = h0; hp.y = h1;
    lp.x = __float2bfloat16(v.x - __bfloat162float(h0));
    lp.y = __float2bfloat16(v.y - __bfloat162float(h1));
    ((__nv_bfloat162*)dh)[i] = hp;
    ((__nv_bfloat162*)dl)[i] = lp;
}
#define PREP1_TOTAL (2 * N2IN + CCH*CCH/2 + 2 * CCH*CCH + NB * HW)

/* ---------------- tsplit both inputs: z = sel*NB + b ---------------- */
__global__ void k_tsplit(const float* __restrict__ in1, const float* __restrict__ in2)
{
    __shared__ float t[32][33];
    int z = blockIdx.z, sel = z / NB, b = z % NB;
    const float* src = sel ? in2 : in1;
    __nv_bfloat16* dh = sel ? g_qt_h : g_ext_h;
    __nv_bfloat16* dl = sel ? g_qt_l : g_ext_l;
    int c0 = blockIdx.y * 32, n0 = blockIdx.x * 32;
    int tx = threadIdx.x, ty = threadIdx.y;
#pragma unroll
    for (int i = 0; i < 4; ++i)
        t[ty + i * 8][tx] = src[((size_t)b * CCH + c0 + ty + i * 8) * HW + n0 + tx];
    __syncthreads();
#pragma unroll
    for (int i = 0; i < 4; ++i) {
        float v = t[tx][ty + i * 8];
        size_t o = ((size_t)b * HW + n0 + ty + i * 8) * CCH + c0 + tx;
        __nv_bfloat16 h = __float2bfloat16(v);
        dh[o] = h;
        dl[o] = __float2bfloat16(v - __bfloat162float(h));
    }
}

/* ---------------- launch ---------------- */
extern "C" void kernel_launch(void* const* d_in, const int* in_sizes, int n_in,
                              void* d_out, int out_size)
{
    const float* in1 = (const float*)d_in[0];
    const float* in2 = (const float*)d_in[1];
    const float* We  = (const float*)d_in[2];
    const float* gw  = (const float*)d_in[3];
    const float* W1  = (const float*)d_in[4];
    const float* W2  = (const float*)d_in[5];
    float* out = (float*)d_out;

    cudaFuncSetAttribute(k_g1,   cudaFuncAttributeMaxDynamicSharedMemorySize, SM_GEMM);
    cudaFuncSetAttribute(k_g2,   cudaFuncAttributeMaxDynamicSharedMemorySize, SM_GEMM);
    cudaFuncSetAttribute(k_att,  cudaFuncAttributeMaxDynamicSharedMemorySize, SM_GEMM);
    cudaFuncSetAttribute(k_conv, cudaFuncAttributeMaxDynamicSharedMemorySize, SM_GEMM);

    k_prep1<<<(PREP1_TOTAL + 255) / 256, 256>>>(in1, in2, We, W1, W2);           /* #1 */
    k_tsplit<<<dim3(HW / 32, CCH / 32, NB * 2), dim3(32, 8)>>>(in1, in2);        /* #2 */
    k_g1<<<dim3(CCH / 128, HW / 128, NB), NTHR, SM_GEMM>>>();                    /* #3 */
    k_g2<<<dim3(HW / 128, HW / 128, NB), NTHR, SM_GEMM>>>();                     /* #4 <- ncu */
    k_att<<<dim3(CCH / 128, HW / 128, NB * 2), NTHR, SM_GEMM>>>();               /* #5 */
    k_ew3<<<dim3(NB * HW / 8, 2), 256>>>(gw);                                    /* #6 */
    k_conv<<<dim3(HW / 128, CCH / 128, NB * 2), NTHR, SM_GEMM>>>(out);           /* #7 */
}

// round 15
// speedup vs baseline: 4.1455x; 1.1242x over previous
#include <cuda_runtime.h>
#include <cuda_bf16.h>
#include <mma.h>
#include <cstdint>
#include <math.h>

using namespace nvcuda;

#define NB 4
#define CCH 256
#define HW 4096

#define LDT 40                  /* k-major tile row stride, elements */
#define LDW 136                 /* row-major-B tile row stride, elements (272B) */
#define TILEA 10240             /* bytes per operand tile slot */
#define STGB (4 * TILEA)        /* Ah+Al+Bh+Bl per stage = 40960 B */
#define NSTG 2
#define SM_GEMM (NSTG * STGB)   /* 81920 B */
#define NTHR 128

typedef wmma::fragment<wmma::matrix_a, 16, 16, 16, __nv_bfloat16, wmma::row_major> FragA;
typedef wmma::fragment<wmma::matrix_b, 16, 16, 16, __nv_bfloat16, wmma::col_major> FragB;
typedef wmma::fragment<wmma::matrix_b, 16, 16, 16, __nv_bfloat16, wmma::row_major> FragBR;
typedef wmma::fragment<wmma::accumulator, 16, 16, 16, float> FragC;

/* ---------------- scratch (no cudaMalloc allowed) ---------------- */
#define SZ_CN ((size_t)NB * CCH * HW)
#define SZ_EE ((size_t)NB * HW * HW)
static __device__ __align__(16) __nv_bfloat16 g_ex_h[SZ_CN], g_ex_l[SZ_CN];
static __device__ __align__(16) __nv_bfloat16 g_q_h[SZ_CN],  g_q_l[SZ_CN];
static __device__ __align__(16) __nv_bfloat16 g_ext_h[SZ_CN], g_ext_l[SZ_CN];
static __device__ __align__(16) __nv_bfloat16 g_qt_h[SZ_CN],  g_qt_l[SZ_CN];
static __device__ __align__(16) __nv_bfloat16 g_We_h[CCH*CCH], g_We_l[CCH*CCH];
static __device__ __align__(16) __nv_bfloat16 g_W1_h[CCH*2*CCH], g_W1_l[CCH*2*CCH];
static __device__ __align__(16) __nv_bfloat16 g_W2_h[CCH*2*CCH], g_W2_l[CCH*2*CCH];
static __device__ __align__(16) __nv_bfloat16 g_ec_h[SZ_CN], g_ec_l[SZ_CN];
static __device__ __align__(16) __nv_bfloat16 g_En_h[SZ_EE], g_En_l[SZ_EE];
static __device__ __align__(16) __nv_bfloat16 g_qatt_h[SZ_CN], g_qatt_l[SZ_CN];
static __device__ __align__(16) __nv_bfloat16 g_eatt_h[SZ_CN], g_eatt_l[SZ_CN];
static __device__ __align__(16) float g_qattF[SZ_CN], g_eattF[SZ_CN];
static __device__ float g_colsum[NB*HW], g_rowsum[NB*HW];

__device__ __forceinline__ uint32_t s2u(const void* p) {
    uint32_t a;
    asm("{ .reg .u64 t; cvta.to.shared.u64 t, %1; cvt.u32.u64 %0, t; }" : "=r"(a) : "l"(p));
    return a;
}
__device__ __forceinline__ void cpa16(uint32_t d, const void* g) {
    asm volatile("cp.async.cg.shared.global [%0], [%1], 16;" :: "r"(d), "l"(g));
}

/* ==== wmma 128x128 GEMM core: single K-sweep, merged 3-product split-bf16 ==== */
/* acc += Ah.Bh + Ah.Bl + Al.Bh.  BROW=0: B k-major. BROW=1: B row-major [k][c]. */
template <bool BROW>
__device__ void gemm_core(char* sm, uint32_t smu,
    const __nv_bfloat16* Ah, const __nv_bfloat16* Al, int lda,
    const __nv_bfloat16* B1h, const __nv_bfloat16* B1l,
    const __nv_bfloat16* B2h, const __nv_bfloat16* B2l, int ksplit, int ldb,
    int K, FragC (&acc)[4][4])
{
    const int t = threadIdx.x, wid = t >> 5;
    const int wm = wid >> 1, wn = wid & 1;  /* 2x2 warps: 64x64 tile each */
    const int nch = K / 32;

#pragma unroll
    for (int mf = 0; mf < 4; ++mf)
#pragma unroll
        for (int nf = 0; nf < 4; ++nf)
            wmma::fill_fragment(acc[mf][nf], 0.0f);

    auto issue = [&](int it) {
        int k0 = it * 32;
        const __nv_bfloat16* ah = Ah + k0;
        const __nv_bfloat16* al = Al + k0;
        const __nv_bfloat16* ph = B1h; const __nv_bfloat16* pl = B1l; int kb = k0;
        if (k0 >= ksplit) { ph = B2h; pl = B2l; kb = k0 - ksplit; }
        const __nv_bfloat16* bh = BROW ? ph + (size_t)kb * ldb : ph + kb;
        const __nv_bfloat16* bl = BROW ? pl + (size_t)kb * ldb : pl + kb;
        uint32_t buf = (uint32_t)(it & 1) * STGB;
#pragma unroll
        for (int i = 0; i < 4; ++i) {
            int v = t + i * NTHR;
            int r = v >> 2, c = v & 3;
            cpa16(smu + buf + r * (LDT * 2) + c * 16, ah + (size_t)r * lda + c * 8);
            cpa16(smu + buf + TILEA + r * (LDT * 2) + c * 16, al + (size_t)r * lda + c * 8);
            if (BROW) {
                int rb = v >> 4, cb = v & 15;
                cpa16(smu + buf + 2 * TILEA + rb * (LDW * 2) + cb * 16, bh + (size_t)rb * ldb + cb * 8);
                cpa16(smu + buf + 3 * TILEA + rb * (LDW * 2) + cb * 16, bl + (size_t)rb * ldb + cb * 8);
            } else {
                cpa16(smu + buf + 2 * TILEA + r * (LDT * 2) + c * 16, bh + (size_t)r * ldb + c * 8);
                cpa16(smu + buf + 3 * TILEA + r * (LDT * 2) + c * 16, bl + (size_t)r * ldb + c * 8);
            }
        }
        asm volatile("cp.async.commit_group;" ::: "memory");
    };
    auto comp = [&](int stg) {
        const __nv_bfloat16* Ahs = (const __nv_bfloat16*)(sm + stg * STGB);
        const __nv_bfloat16* Als = (const __nv_bfloat16*)(sm + stg * STGB + TILEA);
        const __nv_bfloat16* Bhs = (const __nv_bfloat16*)(sm + stg * STGB + 2 * TILEA);
        const __nv_bfloat16* Bls = (const __nv_bfloat16*)(sm + stg * STGB + 3 * TILEA);
#pragma unroll
        for (int kk = 0; kk < 32; kk += 16) {
            FragA afh[4], afl[4];
#pragma unroll
            for (int mf = 0; mf < 4; ++mf) {
                wmma::load_matrix_sync(afh[mf], Ahs + (wm * 64 + mf * 16) * LDT + kk, LDT);
                wmma::load_matrix_sync(afl[mf], Als + (wm * 64 + mf * 16) * LDT + kk, LDT);
            }
            if (BROW) {
#pragma unroll
                for (int nf = 0; nf < 4; ++nf) {
                    FragBR bh, bl;
                    wmma::load_matrix_sync(bh, Bhs + kk * LDW + wn * 64 + nf * 16, LDW);
                    wmma::load_matrix_sync(bl, Bls + kk * LDW + wn * 64 + nf * 16, LDW);
#pragma unroll
                    for (int mf = 0; mf < 4; ++mf) {
                        wmma::mma_sync(acc[mf][nf], afh[mf], bh, acc[mf][nf]);
                        wmma::mma_sync(acc[mf][nf], afh[mf], bl, acc[mf][nf]);
                        wmma::mma_sync(acc[mf][nf], afl[mf], bh, acc[mf][nf]);
                    }
                }
            } else {
#pragma unroll
                for (int nf = 0; nf < 4; ++nf) {
                    FragB bh, bl;
                    wmma::load_matrix_sync(bh, Bhs + (wn * 64 + nf * 16) * LDT + kk, LDT);
                    wmma::load_matrix_sync(bl, Bls + (wn * 64 + nf * 16) * LDT + kk, LDT);
#pragma unroll
                    for (int mf = 0; mf < 4; ++mf) {
                        wmma::mma_sync(acc[mf][nf], afh[mf], bh, acc[mf][nf]);
                        wmma::mma_sync(acc[mf][nf], afh[mf], bl, acc[mf][nf]);
                        wmma::mma_sync(acc[mf][nf], afl[mf], bh, acc[mf][nf]);
                    }
                }
            }
        }
    };

    issue(0);
    for (int it = 0; it < nch; ++it) {
        if (it + 1 < nch) {
            issue(it + 1);
            asm volatile("cp.async.wait_group 1;" ::: "memory");
        } else {
            asm volatile("cp.async.wait_group 0;" ::: "memory");
        }
        __syncthreads();
        comp(it & 1);
        __syncthreads();
    }
}

__device__ __forceinline__ void store_c(FragC (&acc)[4][4], float* C, int ldc)
{
    int wid = threadIdx.x >> 5, wm = wid >> 1, wn = wid & 1;
#pragma unroll
    for (int mf = 0; mf < 4; ++mf)
#pragma unroll
        for (int nf = 0; nf < 4; ++nf)
            wmma::store_matrix_sync(C + (size_t)(wm * 64 + mf * 16) * ldc + wn * 64 + nf * 16,
                                    acc[mf][nf], ldc, wmma::mem_row_major);
}
__device__ __forceinline__ void store_c_col(FragC (&acc)[4][4], float* C, int ldc)
{
    int wid = threadIdx.x >> 5, wm = wid >> 1, wn = wid & 1;
#pragma unroll
    for (int mf = 0; mf < 4; ++mf)
#pragma unroll
        for (int nf = 0; nf < 4; ++nf)
            wmma::store_matrix_sync(C + (size_t)(wn * 64 + nf * 16) * ldc + wm * 64 + mf * 16,
                                    acc[mf][nf], ldc, wmma::mem_col_major);
}

/* ---- epilogue: stage 64-row halves, write hi/lo split, 128 threads ---- */
__device__ void epilogue_split(char* sm, FragC (&acc)[4][4],
    __nv_bfloat16* dh, __nv_bfloat16* dl, size_t rowbase, int ldo)
{
    int t = threadIdx.x, wid = t >> 5, wm = wid >> 1, wn = wid & 1;
    float* stg = (float*)sm;
    const int LDS2 = 132;
    for (int h = 0; h < 2; ++h) {
        __syncthreads();
        if (wm == h) {
#pragma unroll
            for (int mf = 0; mf < 4; ++mf)
#pragma unroll
                for (int nf = 0; nf < 4; ++nf)
                    wmma::store_matrix_sync(stg + (mf * 16) * LDS2 + wn * 64 + nf * 16,
                                            acc[mf][nf], LDS2, wmma::mem_row_major);
        }
        __syncthreads();
        int row = t >> 1, seg = t & 1;
        const float* sp = stg + row * LDS2 + seg * 64;
        size_t o = rowbase + (size_t)(h * 64 + row) * ldo + seg * 64;
#pragma unroll
        for (int q = 0; q < 8; ++q) {
            __nv_bfloat162 hv[4], lv[4];
#pragma unroll
            for (int j = 0; j < 4; ++j) {
                float a = sp[q * 8 + 2 * j], c2 = sp[q * 8 + 2 * j + 1];
                __nv_bfloat16 ha = __float2bfloat16(a), hc = __float2bfloat16(c2);
                hv[j].x = ha; hv[j].y = hc;
                lv[j].x = __float2bfloat16(a - __bfloat162float(ha));
                lv[j].y = __float2bfloat16(c2 - __bfloat162float(hc));
            }
            *(uint4*)(dh + o + q * 8) = *(uint4*)hv;
            *(uint4*)(dl + o + q * 8) = *(uint4*)lv;
        }
    }
}

/* ---------------- GEMM1: ec[n][d] (hi/lo) = ext[n][:] . We[d][:] ---------------- */
__global__ __launch_bounds__(NTHR, 2) void k_g1()
{
    extern __shared__ __align__(128) char sm[];
    uint32_t smu = s2u(sm);
    int b = blockIdx.z, r0 = blockIdx.y * 128, c0 = blockIdx.x * 128;
    FragC acc[4][4];
    size_t ao = ((size_t)b * HW + r0) * CCH;
    gemm_core<false>(sm, smu, g_ext_h + ao, g_ext_l + ao, CCH,
              g_We_h + (size_t)c0 * CCH, g_We_l + (size_t)c0 * CCH,
              g_We_h + (size_t)c0 * CCH, g_We_l + (size_t)c0 * CCH, 1 << 30, CCH, CCH, acc);
    epilogue_split(sm, acc, g_ec_h, g_ec_l, ao + c0, CCH);
}

/* ---- GEMM2 + fused epilogue: E=__expf(ec.qt^T); En hi/lo; row/col sums ---- */
__global__ __launch_bounds__(NTHR, 2) void k_g2()
{
    extern __shared__ __align__(128) char sm[];
    uint32_t smu = s2u(sm);
    int b = blockIdx.z, r0 = blockIdx.y * 128, c0 = blockIdx.x * 128;
    int t = threadIdx.x, wid = t >> 5, wm = wid >> 1, wn = wid & 1;
    FragC acc[4][4];
    size_t ao = ((size_t)b * HW + r0) * CCH, bo = ((size_t)b * HW + c0) * CCH;
    gemm_core<false>(sm, smu, g_ec_h + ao, g_ec_l + ao, CCH,
              g_qt_h + bo, g_qt_l + bo, g_qt_h + bo, g_qt_l + bo, 1 << 30, CCH, CCH, acc);

#pragma unroll
    for (int mf = 0; mf < 4; ++mf)
#pragma unroll
        for (int nf = 0; nf < 4; ++nf)
#pragma unroll
            for (int i = 0; i < acc[mf][nf].num_elements; ++i)
                acc[mf][nf].x[i] = __expf(acc[mf][nf].x[i]);

    float* stg = (float*)sm;
    const int LDS2 = 132;
    float csum = 0.f;
    for (int h = 0; h < 2; ++h) {
        __syncthreads();
        if (wm == h) {
#pragma unroll
            for (int mf = 0; mf < 4; ++mf)
#pragma unroll
                for (int nf = 0; nf < 4; ++nf)
                    wmma::store_matrix_sync(stg + (mf * 16) * LDS2 + wn * 64 + nf * 16,
                                            acc[mf][nf], LDS2, wmma::mem_row_major);
        }
        __syncthreads();
        {
            int row = t >> 1, seg = t & 1;
            const float* sp = stg + row * LDS2 + seg * 64;
            size_t o = ((size_t)b * HW + r0 + h * 64 + row) * HW + c0 + seg * 64;
            float rs = 0.f;
#pragma unroll
            for (int q = 0; q < 8; ++q) {
                __nv_bfloat162 hv[4], lv[4];
#pragma unroll
                for (int j = 0; j < 4; ++j) {
                    float a = sp[q * 8 + 2 * j], c2 = sp[q * 8 + 2 * j + 1];
                    rs += a + c2;
                    __nv_bfloat16 ha = __float2bfloat16(a), hc = __float2bfloat16(c2);
                    hv[j].x = ha; hv[j].y = hc;
                    lv[j].x = __float2bfloat16(a - __bfloat162float(ha));
                    lv[j].y = __float2bfloat16(c2 - __bfloat162float(hc));
                }
                *(uint4*)(g_En_h + o + q * 8) = *(uint4*)hv;
                *(uint4*)(g_En_l + o + q * 8) = *(uint4*)lv;
            }
            rs += __shfl_xor_sync(~0u, rs, 1);
            if (seg == 0) atomicAdd(&g_rowsum[b * HW + r0 + h * 64 + row], rs);
        }
        {
            const float* sp = stg + t;
#pragma unroll
            for (int j = 0; j < 64; ++j) csum += sp[j * LDS2];
        }
    }
    atomicAdd(&g_colsum[b * HW + c0 + t], csum);
}

/* ------ GEMM3/4 merged (both read only En): z -> (b, sel) ------ */
__global__ __launch_bounds__(NTHR, 2) void k_att()
{
    extern __shared__ __align__(128) char sm[];
    uint32_t smu = s2u(sm);
    int z = blockIdx.z, b = z >> 1, sel = z & 1;
    FragC acc[4][4];
    if (sel == 1) {
        int r0 = blockIdx.y * 128, c0 = blockIdx.x * 128;
        size_t ao = ((size_t)b * HW + r0) * HW, bo = ((size_t)b * CCH + c0) * HW;
        gemm_core<false>(sm, smu, g_En_h + ao, g_En_l + ao, HW,
                  g_q_h + bo, g_q_l + bo, g_q_h + bo, g_q_l + bo, 1 << 30, HW, HW, acc);
        __syncthreads();
        store_c(acc, g_eattF + ((size_t)b * HW + r0) * CCH + c0, CCH);
    } else {
        int cblk = blockIdx.x * 128, m0 = blockIdx.y * 128;
        size_t ao = ((size_t)b * CCH + cblk) * HW;
        const __nv_bfloat16* Bh = g_En_h + (size_t)b * HW * HW + m0;
        const __nv_bfloat16* Bl = g_En_l + (size_t)b * HW * HW + m0;
        gemm_core<true>(sm, smu, g_ex_h + ao, g_ex_l + ao, HW,
                  Bh, Bl, Bh, Bl, 1 << 30, HW, HW, acc);
        __syncthreads();
        store_c_col(acc, g_qattF + ((size_t)b * HW + m0) * CCH + cblk, CCH);
    }
}

/* ------ conv merged: out[o][x] = W[o][0:512].[att|inp_t][x][0:512]; z -> (b, w) ------ */
__global__ __launch_bounds__(NTHR, 2) void k_conv(float* __restrict__ out)
{
    extern __shared__ __align__(128) char sm[];
    uint32_t smu = s2u(sm);
    int z = blockIdx.z, b = z >> 1, w = z & 1;
    int o0 = blockIdx.y * 128, x0 = blockIdx.x * 128;
    const __nv_bfloat16 *Wh, *Wl, *B1h, *B1l, *B2h, *B2l;
    if (w == 0) { Wh = g_W1_h; Wl = g_W1_l; B1h = g_eatt_h; B1l = g_eatt_l; B2h = g_ext_h; B2l = g_ext_l; }
    else        { Wh = g_W2_h; Wl = g_W2_l; B1h = g_qatt_h; B1l = g_qatt_l; B2h = g_qt_h;  B2l = g_qt_l; }
    FragC acc[4][4];
    size_t bo = ((size_t)b * HW + x0) * CCH;
    gemm_core<false>(sm, smu, Wh + (size_t)o0 * 512, Wl + (size_t)o0 * 512, 512,
              B1h + bo, B1l + bo, B2h + bo, B2l + bo, 256, CCH, 512, acc);
    __syncthreads();
    store_c(acc, out + (size_t)w * SZ_CN + ((size_t)b * CCH + o0) * HW + x0, HW);
}

/* ---------------- ew3 merged: normalize + gate + split; y -> sel ---------------- */
__global__ __launch_bounds__(256) void k_ew3(const float* __restrict__ gw)
{
    __shared__ float sgw[256];
    int tid = threadIdx.x, lane = tid & 31, wid = tid >> 5;
    int sel = blockIdx.y;
    sgw[tid] = gw[tid];
    __syncthreads();
    const float* af = sel ? g_eattF : g_qattF;
    const float* sums = sel ? g_rowsum : g_colsum;
    __nv_bfloat16* oh = sel ? g_eatt_h : g_qatt_h;
    __nv_bfloat16* ol = sel ? g_eatt_l : g_qatt_l;
    size_t row = (size_t)blockIdx.x * 8 + wid;
    float4 v0 = *(const float4*)(af + row * 256 + lane * 8);
    float4 v1 = *(const float4*)(af + row * 256 + lane * 8 + 4);
    float v[8] = {v0.x, v0.y, v0.z, v0.w, v1.x, v1.y, v1.z, v1.w};
    float dot = 0.f;
#pragma unroll
    for (int j = 0; j < 8; ++j) dot += v[j] * sgw[lane * 8 + j];
#pragma unroll
    for (int m = 16; m; m >>= 1) dot += __shfl_xor_sync(~0u, dot, m);
    float inv = 1.f / sums[row];
    float s = inv / (1.f + expf(-inv * dot));
    __nv_bfloat162 hq[4], lq[4];
#pragma unroll
    for (int j = 0; j < 4; ++j) {
        float a = v[2 * j] * s, c = v[2 * j + 1] * s;
        __nv_bfloat16 ha = __float2bfloat16(a), hc = __float2bfloat16(c);
        hq[j].x = ha; hq[j].y = hc;
        lq[j].x = __float2bfloat16(a - __bfloat162float(ha));
        lq[j].y = __float2bfloat16(c - __bfloat162float(hc));
    }
    *(uint4*)(oh + row * 256 + lane * 8) = *(uint4*)hq;
    *(uint4*)(ol + row * 256 + lane * 8) = *(uint4*)lq;
}

/* ---------------- prep1: ALL linear splits + zero, one launch ---------------- */
#define N2IN ((int)(SZ_CN / 2))
__global__ void k_prep1(const float* __restrict__ in1, const float* __restrict__ in2,
                        const float* __restrict__ We, const float* __restrict__ W1,
                        const float* __restrict__ W2)
{
    int idx = blockIdx.x * 256 + threadIdx.x;
    const float* src; __nv_bfloat16 *dh, *dl; int i = idx;
    if (idx < N2IN)                         { src = in1; dh = g_ex_h; dl = g_ex_l; }
    else if ((i -= N2IN) < N2IN)            { src = in2; dh = g_q_h;  dl = g_q_l;  }
    else if ((i -= N2IN) < CCH*CCH/2)       { src = We;  dh = g_We_h; dl = g_We_l; }
    else if ((i -= CCH*CCH/2) < CCH*CCH)    { src = W1;  dh = g_W1_h; dl = g_W1_l; }
    else if ((i -= CCH*CCH) < CCH*CCH)      { src = W2;  dh = g_W2_h; dl = g_W2_l; }
    else {
        i -= CCH*CCH;
        if (i < NB * HW) { g_colsum[i] = 0.f; g_rowsum[i] = 0.f; }
        return;
    }
    float2 v = ((const float2*)src)[i];
    __nv_bfloat16 h0 = __float2bfloat16(v.x), h1 = __float2bfloat16(v.y);
    __nv_bfloat162 hp, lp;
    hp.x = h0; hp.y = h1;
    lp.x = __float2bfloat16(v.x - __bfloat162float(h0));
    lp.y = __float2bfloat16(v.y - __bfloat162float(h1));
    ((__nv_bfloat162*)dh)[i] = hp;
    ((__nv_bfloat162*)dl)[i] = lp;
}
#define PREP1_TOTAL (2 * N2IN + CCH*CCH/2 + 2 * CCH*CCH + NB * HW)

/* ---------------- tsplit both inputs: z = sel*NB + b ---------------- */
__global__ void k_tsplit(const float* __restrict__ in1, const float* __restrict__ in2)
{
    __shared__ float t[32][33];
    int z = blockIdx.z, sel = z / NB, b = z % NB;
    const float* src = sel ? in2 : in1;
    __nv_bfloat16* dh = sel ? g_qt_h : g_ext_h;
    __nv_bfloat16* dl = sel ? g_qt_l : g_ext_l;
    int c0 = blockIdx.y * 32, n0 = blockIdx.x * 32;
    int tx = threadIdx.x, ty = threadIdx.y;
#pragma unroll
    for (int i = 0; i < 4; ++i)
        t[ty + i * 8][tx] = src[((size_t)b * CCH + c0 + ty + i * 8) * HW + n0 + tx];
    __syncthreads();
#pragma unroll
    for (int i = 0; i < 4; ++i) {
        float v = t[tx][ty + i * 8];
        size_t o = ((size_t)b * HW + n0 + ty + i * 8) * CCH + c0 + tx;
        __nv_bfloat16 h = __float2bfloat16(v);
        dh[o] = h;
        dl[o] = __float2bfloat16(v - __bfloat162float(h));
    }
}

/* ---------------- launch ---------------- */
extern "C" void kernel_launch(void* const* d_in, const int* in_sizes, int n_in,
                              void* d_out, int out_size)
{
    const float* in1 = (const float*)d_in[0];
    const float* in2 = (const float*)d_in[1];
    const float* We  = (const float*)d_in[2];
    const float* gw  = (const float*)d_in[3];
    const float* W1  = (const float*)d_in[4];
    const float* W2  = (const float*)d_in[5];
    float* out = (float*)d_out;

    cudaFuncSetAttribute(k_g1,   cudaFuncAttributeMaxDynamicSharedMemorySize, SM_GEMM);
    cudaFuncSetAttribute(k_g2,   cudaFuncAttributeMaxDynamicSharedMemorySize, SM_GEMM);
    cudaFuncSetAttribute(k_att,  cudaFuncAttributeMaxDynamicSharedMemorySize, SM_GEMM);
    cudaFuncSetAttribute(k_conv, cudaFuncAttributeMaxDynamicSharedMemorySize, SM_GEMM);

    k_prep1<<<(PREP1_TOTAL + 255) / 256, 256>>>(in1, in2, We, W1, W2);           /* #1 */
    k_tsplit<<<dim3(HW / 32, CCH / 32, NB * 2), dim3(32, 8)>>>(in1, in2);        /* #2 */
    k_g1<<<dim3(CCH / 128, HW / 128, NB), NTHR, SM_GEMM>>>();                    /* #3 */
    k_g2<<<dim3(HW / 128, HW / 128, NB), NTHR, SM_GEMM>>>();                     /* #4 <- ncu */
    k_att<<<dim3(CCH / 128, HW / 128, NB * 2), NTHR, SM_GEMM>>>();               /* #5 */
    k_ew3<<<dim3(NB * HW / 8, 2), 256>>>(gw);                                    /* #6 */
    k_conv<<<dim3(HW / 128, CCH / 128, NB * 2), NTHR, SM_GEMM>>>(out);           /* #7 */
}